// round 13
// baseline (speedup 1.0000x reference)
#include <cuda_runtime.h>
#include <cuda_fp16.h>
#include <stdint.h>

// ---------------------------------------------------------------------------
// GCN 2-layer, fp16 tensor-core GEMMs (m16n8k16, fp32 accum), fp16 feature
// buffers, CSR pull aggregation. Pipelined two-stream schedule:
//   stream0: W1^T -> GEMM1a(cols 0-255) -> GEMM1b(cols 256-511)
//            -> pull1 c2,c3 -> GEMM2 -> pull2
//   streamB: init -> hist -> scan -> dinv -> scatter -> W2^T
//            -> (after GEMM1a) pull1 c0,c1
// GEMM1 converts x fp32->fp16 in its A staging (no xcvt pass).
// ---------------------------------------------------------------------------

#define MAXN 100352
#define MAXE 1048576

__device__ __half g_h16[(size_t)MAXN * 512];
__device__ __half g_agg16[(size_t)MAXN * 512];
__device__ __half g_hs2h[(size_t)MAXN * 128];
__device__ __half g_wt1[(size_t)512 * 512];
__device__ __half g_wt2[(size_t)128 * 512];
__device__ float  g_dinv[MAXN];
__device__ int    g_cnt[MAXN];
__device__ int    g_rowp[MAXN + 1];
__device__ int    g_cur[MAXN];
__device__ int    g_col[MAXE];
__device__ int    g_bsum[1025];
__device__ int    g_is64;

// --------- side stream + events, created pre-main (global ctor) ------------
struct StreamHolder {
    cudaStream_t s;
    cudaEvent_t  e0, eA, eCSR, eB;
    bool ok;
    StreamHolder() {
        ok = (cudaStreamCreateWithFlags(&s, cudaStreamNonBlocking) == cudaSuccess);
        ok = ok && (cudaEventCreateWithFlags(&e0,   cudaEventDisableTiming) == cudaSuccess);
        ok = ok && (cudaEventCreateWithFlags(&eA,   cudaEventDisableTiming) == cudaSuccess);
        ok = ok && (cudaEventCreateWithFlags(&eCSR, cudaEventDisableTiming) == cudaSuccess);
        ok = ok && (cudaEventCreateWithFlags(&eB,   cudaEventDisableTiming) == cudaSuccess);
        if (!ok) s = 0;
    }
};
static StreamHolder g_sh;

// ------------------------------- helpers -----------------------------------
__device__ __forceinline__ uint32_t smem_u32(const void* p) {
    uint32_t a;
    asm("{ .reg .u64 t; cvta.to.shared.u64 t, %1; cvt.u32.u64 %0, t; }" : "=r"(a) : "l"(p));
    return a;
}
__device__ __forceinline__ void ldsm_x4(uint32_t& r0, uint32_t& r1, uint32_t& r2, uint32_t& r3,
                                        uint32_t addr) {
    asm volatile("ldmatrix.sync.aligned.m8n8.x4.shared.b16 {%0,%1,%2,%3}, [%4];"
                 : "=r"(r0), "=r"(r1), "=r"(r2), "=r"(r3) : "r"(addr));
}
__device__ __forceinline__ void cp_async16(uint32_t dst, const void* src) {
    asm volatile("cp.async.ca.shared.global [%0], [%1], 16;" :: "r"(dst), "l"(src) : "memory");
}
#define CP_COMMIT() asm volatile("cp.async.commit_group;" ::: "memory")
#define CP_WAIT0()  asm volatile("cp.async.wait_group 0;" ::: "memory")
#define CP_WAIT1()  asm volatile("cp.async.wait_group 1;" ::: "memory")

#define MMA16816(acc, af, bf)                                                  \
    asm volatile(                                                              \
        "mma.sync.aligned.m16n8k16.row.col.f32.f16.f16.f32 "                   \
        "{%0,%1,%2,%3}, {%4,%5,%6,%7}, {%8,%9}, {%0,%1,%2,%3};"                \
        : "+f"((acc)[0]), "+f"((acc)[1]), "+f"((acc)[2]), "+f"((acc)[3])       \
        : "r"((af)[0]), "r"((af)[1]), "r"((af)[2]), "r"((af)[3]),              \
          "r"((bf)[0]), "r"((bf)[1]))

__device__ __forceinline__ long long edge_at(const void* ei, long long idx, int is64) {
    if (is64) return ((const long long*)ei)[idx];
    return (long long)((const int*)ei)[idx];
}

// ---------------------------------------------------------------------------
__global__ void k_init(const void* ei, long long nelem, int n, int* cnt) {
    int i = blockIdx.x * blockDim.x + threadIdx.x;
    if (i < n) cnt[i] = 0;
    if (blockIdx.x == 0 && threadIdx.x == 0) {
        const long long* p = (const long long*)ei;
        long long m = 64;
        if (m > nelem / 2) m = nelem / 2;
        int is64 = 1;
        for (long long j = 0; j < m; j++) {
            long long v = p[j];
            if (v < 0 || v >= (long long)n) { is64 = 0; break; }
        }
        g_is64 = is64;
    }
}

__global__ void k_transpose_h(const float* __restrict__ W, __half* __restrict__ Wt, int K, int N) {
    __shared__ float tile[32][33];
    int k0 = blockIdx.y * 32, n0 = blockIdx.x * 32;
    int tx = threadIdx.x, ty = threadIdx.y;  // 32 x 8
    for (int j = 0; j < 32; j += 8)
        tile[ty + j][tx] = W[(size_t)(k0 + ty + j) * N + n0 + tx];
    __syncthreads();
    for (int j = 0; j < 32; j += 8)
        Wt[(size_t)(n0 + ty + j) * K + k0 + tx] = __float2half_rn(tile[tx][ty + j]);
}

__global__ void k_hist(const void* __restrict__ ei, long long E, int* __restrict__ cnt) {
    long long i = (long long)blockIdx.x * blockDim.x + threadIdx.x;
    if (i >= E) return;
    int d = (int)edge_at(ei, E + i, g_is64);
    atomicAdd(&cnt[d], 1);
}

__global__ void k_scan_blk(const int* __restrict__ cnt, int* __restrict__ rowp,
                           int* __restrict__ bsum, int n) {
    __shared__ int warpsum[32];
    const int t = threadIdx.x, lane = t & 31, w = t >> 5;
    int i = blockIdx.x * 1024 + t;
    int v = (i < n) ? cnt[i] : 0;
    int x = v;
#pragma unroll
    for (int off = 1; off < 32; off <<= 1) {
        int y = __shfl_up_sync(0xFFFFFFFFu, x, off);
        if (lane >= off) x += y;
    }
    if (lane == 31) warpsum[w] = x;
    __syncthreads();
    if (w == 0) {
        int s = warpsum[lane];
#pragma unroll
        for (int off = 1; off < 32; off <<= 1) {
            int y = __shfl_up_sync(0xFFFFFFFFu, s, off);
            if (lane >= off) s += y;
        }
        warpsum[lane] = s;
    }
    __syncthreads();
    int wpre = (w > 0) ? warpsum[w - 1] : 0;
    if (i < n) rowp[i] = x - v + wpre;
    if (t == 1023) bsum[blockIdx.x] = wpre + x;
}

__global__ void k_scan_top(int* __restrict__ bsum, int nb) {
    __shared__ int warpsum[32];
    const int t = threadIdx.x, lane = t & 31, w = t >> 5;
    int v = (t < nb) ? bsum[t] : 0;
    int x = v;
#pragma unroll
    for (int off = 1; off < 32; off <<= 1) {
        int y = __shfl_up_sync(0xFFFFFFFFu, x, off);
        if (lane >= off) x += y;
    }
    if (lane == 31) warpsum[w] = x;
    __syncthreads();
    if (w == 0) {
        int s = warpsum[lane];
#pragma unroll
        for (int off = 1; off < 32; off <<= 1) {
            int y = __shfl_up_sync(0xFFFFFFFFu, s, off);
            if (lane >= off) s += y;
        }
        warpsum[lane] = s;
    }
    __syncthreads();
    int wpre = (w > 0) ? warpsum[w - 1] : 0;
    if (t < nb) bsum[t] = x - v + wpre;
    if (t == 1023) bsum[nb] = warpsum[31];
}

__global__ void k_scan_add(int* __restrict__ rowp, const int* __restrict__ bsum, int n, int nb) {
    int i = blockIdx.x * blockDim.x + threadIdx.x;
    if (i < n) rowp[i] += bsum[i >> 10];
    if (i == n) rowp[n] = bsum[nb];
}

__global__ void k_dinv_cursor(const int* __restrict__ cnt, const int* __restrict__ rowp,
                              float* __restrict__ dinv, int* __restrict__ cur, int n) {
    int i = blockIdx.x * blockDim.x + threadIdx.x;
    if (i >= n) return;
    dinv[i] = rsqrtf((float)cnt[i] + 1.0f);
    cur[i]  = rowp[i];
}

__global__ void k_scatter(const void* __restrict__ ei, long long E,
                          int* __restrict__ cur, int* __restrict__ colA) {
    long long i = (long long)blockIdx.x * blockDim.x + threadIdx.x;
    if (i >= E) return;
    int is64 = g_is64;
    int s = (int)edge_at(ei, i, is64);
    int d = (int)edge_at(ei, E + i, is64);
    int pos = atomicAdd(&cur[d], 1);
    colA[pos] = s;
}

// ---------------------------------------------------------------------------
// GEMM1 (half-N launch): H16[M, ncol0:ncol0+256] = X[M,512] @ Wt[:,512]^T
// Block 128x256, 512 threads (16 warps 4x4), warp tile 32x64, BK=32.
// A staged from fp32 X via LDG+cvt+STS (one stage held in regs);
// B staged via 3-stage cp.async. One barrier per ktile.
// ---------------------------------------------------------------------------
#define G1_SMEM (3 * (8192 + 16384))

__global__ __launch_bounds__(512, 1)
void k_gemm_big(const float* __restrict__ X, const __half* __restrict__ Bt,
                __half* __restrict__ H, int M, int ncol0)
{
    extern __shared__ __align__(16) char smem[];
    const uint32_t sbA = smem_u32(smem);
    const uint32_t sbB = sbA + 3 * 8192;

    const int t   = threadIdx.x;
    const int L   = t & 31;
    const int wid = t >> 5;
    const int wm  = wid >> 2;
    const int wn  = wid & 3;
    const int g   = L >> 2;
    const int c   = L & 3;
    const int m0  = blockIdx.y * 128;
    const int n0  = ncol0;

    const uint32_t aLane = ((uint32_t)((L >> 4) & 1)) * 128u
                         + (uint32_t)(wm * 32) + (uint32_t)(L & 7) + ((uint32_t)((L >> 3) & 1)) * 8u;
    const uint32_t bLane = ((uint32_t)((L >> 3) & 1)) * 256u
                         + (uint32_t)(wn * 64) + (uint32_t)(L & 7) + ((uint32_t)((L >> 4) & 1)) * 8u;

    // staging: A 512 slots -> 1/thread; B 1024 slots -> 2/thread
    const int a_row = t & 127, a_k8 = t >> 7;
    const bool mval = (m0 + a_row) < M;
    const int b_r0  = t & 255, b_k0 = t >> 8;
    const int b_r1  = b_r0,    b_k1 = b_k0 + 2;

    float acc[2][8][4];
#pragma unroll
    for (int i = 0; i < 2; i++)
#pragma unroll
        for (int j = 0; j < 8; j++)
#pragma unroll
            for (int q = 0; q < 4; q++) acc[i][j][q] = 0.0f;

    float4 ra0, ra1;  // A slot held one stage ahead

    auto ldA = [&](int kt) {
        const float* ga = X + (size_t)(m0 + a_row) * 512 + kt * 32 + a_k8 * 8;
        ra0 = mval ? *(const float4*)ga       : make_float4(0, 0, 0, 0);
        ra1 = mval ? *(const float4*)(ga + 4) : make_float4(0, 0, 0, 0);
    };
    auto stsA = [&](int kt) {
        const int stg = kt % 3;
        __half2 h0 = __floats2half2_rn(ra0.x, ra0.y);
        __half2 h1 = __floats2half2_rn(ra0.z, ra0.w);
        __half2 h2 = __floats2half2_rn(ra1.x, ra1.y);
        __half2 h3 = __floats2half2_rn(ra1.z, ra1.w);
        *(uint4*)(smem + stg * 8192 + t * 16) =
            make_uint4(*(uint32_t*)&h0, *(uint32_t*)&h1, *(uint32_t*)&h2, *(uint32_t*)&h3);
    };
    auto cpB = [&](int kt) {
        const int stg = kt % 3;
        const int k0 = kt * 32;
        uint32_t bbase = sbB + stg * 16384u;
        cp_async16(bbase + (uint32_t)t * 16u,
                   Bt + (size_t)(n0 + b_r0) * 512 + k0 + b_k0 * 8);
        cp_async16(bbase + (uint32_t)(t + 512) * 16u,
                   Bt + (size_t)(n0 + b_r1) * 512 + k0 + b_k1 * 8);
        CP_COMMIT();
    };

    // prologue
    ldA(0); stsA(0);
    ldA(1);
    cpB(0);
    cpB(1);

    for (int kt = 0; kt < 16; kt++) {
        if (kt + 1 < 16) { CP_WAIT1(); } else { CP_WAIT0(); }
        __syncthreads();   // publishes A(kt) stores + B(kt) visibility

        // store next A stage (stage (kt+1)%3 last read at compute(kt-2): safe),
        // then start loads for kt+2
        if (kt + 1 < 16) stsA(kt + 1);
        if (kt + 2 < 16) { ldA(kt + 2); cpB(kt + 2); }

        const int stg = kt % 3;
        const uint32_t aB = sbA + stg * 8192u;
        const uint32_t bB = sbB + stg * 16384u;
#pragma unroll
        for (int kk = 0; kk < 2; kk++) {
            uint32_t af[2][4];
            uint32_t bf[8][2];
#pragma unroll
            for (int fm = 0; fm < 2; fm++)
                ldsm_x4(af[fm][0], af[fm][1], af[fm][2], af[fm][3],
                        aB + (aLane + (uint32_t)(kk * 256 + fm * 16)) * 16u);
#pragma unroll
            for (int p = 0; p < 4; p++)
                ldsm_x4(bf[2 * p][0], bf[2 * p][1], bf[2 * p + 1][0], bf[2 * p + 1][1],
                        bB + (bLane + (uint32_t)(kk * 512 + p * 16)) * 16u);
#pragma unroll
            for (int fm = 0; fm < 2; fm++)
#pragma unroll
                for (int fn = 0; fn < 8; fn++)
                    MMA16816(acc[fm][fn], af[fm], bf[fn]);
        }
    }

    // epilogue: raw fp16 store (M-guarded)
#pragma unroll
    for (int fm = 0; fm < 2; fm++) {
        int r0 = m0 + wm * 32 + fm * 16 + g;
        int r1 = r0 + 8;
#pragma unroll
        for (int fn = 0; fn < 8; fn++) {
            int col = n0 + wn * 64 + fn * 8 + c * 2;
            if (r0 < M) {
                __half2 v0 = __floats2half2_rn(acc[fm][fn][0], acc[fm][fn][1]);
                *(__half2*)&H[(size_t)r0 * 512 + col] = v0;
            }
            if (r1 < M) {
                __half2 v1 = __floats2half2_rn(acc[fm][fn][2], acc[fm][fn][3]);
                *(__half2*)&H[(size_t)r1 * 512 + col] = v1;
            }
        }
    }
}

// ---------------------------------------------------------------------------
// GEMM2: Hs2h[M,128] = (A16[M,512] @ Wt2[128,512]^T) * dinv[row]  (fp16 out)
// ---------------------------------------------------------------------------
__global__ __launch_bounds__(256, 2)
void k_gemm2(const __half* __restrict__ A, const __half* __restrict__ Bt,
             const float* __restrict__ dinv, __half* __restrict__ Hs, int M)
{
    __shared__ __align__(16) char smem[32768];
    const uint32_t sbA = smem_u32(smem);
    const uint32_t sbB = sbA + 16384;

    const int t   = threadIdx.x;
    const int L   = t & 31;
    const int wid = t >> 5;
    const int wm  = wid >> 1;
    const int wn  = wid & 1;
    const int g   = L >> 2;
    const int c   = L & 3;
    const int m0  = blockIdx.y * 128;

    const uint32_t aLane = ((uint32_t)((L >> 4) & 1)) * 128u
                         + (uint32_t)(wm * 32) + (uint32_t)(L & 7) + ((uint32_t)((L >> 3) & 1)) * 8u;
    const uint32_t bLane = ((uint32_t)((L >> 3) & 1)) * 128u
                         + (uint32_t)(wn * 64) + (uint32_t)(L & 7) + ((uint32_t)((L >> 4) & 1)) * 8u;

    const int s0 = t, s1 = t + 256;
    const int r0s = s0 & 127, k80 = s0 >> 7;
    const int r1s = s1 & 127, k81 = s1 >> 7;
    const bool m0v = (m0 + r0s) < M, m1v = (m0 + r1s) < M;
    // clamp A row for OOB (value irrelevant, row guarded at store)
    const int ar0 = m0v ? (m0 + r0s) : 0;
    const int ar1 = m1v ? (m0 + r1s) : 0;

    float acc[2][8][4];
#pragma unroll
    for (int i = 0; i < 2; i++)
#pragma unroll
        for (int j = 0; j < 8; j++)
#pragma unroll
            for (int q = 0; q < 4; q++) acc[i][j][q] = 0.0f;

    {
        cp_async16(sbA + s0 * 16u, A + (size_t)ar0 * 512 + k80 * 8);
        cp_async16(sbA + s1 * 16u, A + (size_t)ar1 * 512 + k81 * 8);
        cp_async16(sbB + s0 * 16u, Bt + (size_t)r0s * 512 + k80 * 8);
        cp_async16(sbB + s1 * 16u, Bt + (size_t)r1s * 512 + k81 * 8);
        CP_COMMIT();
        CP_WAIT0();
    }
    __syncthreads();

    for (int kt = 0; kt < 16; kt++) {
        const int buf  = kt & 1;
        const int nbuf = 1 - buf;
        const bool nxt = (kt + 1) < 16;

        if (nxt) {
            const int k0 = (kt + 1) * 32;
            cp_async16(sbA + nbuf * 8192u + s0 * 16u, A + (size_t)ar0 * 512 + k0 + k80 * 8);
            cp_async16(sbA + nbuf * 8192u + s1 * 16u, A + (size_t)ar1 * 512 + k0 + k81 * 8);
            cp_async16(sbB + nbuf * 8192u + s0 * 16u, Bt + (size_t)r0s * 512 + k0 + k80 * 8);
            cp_async16(sbB + nbuf * 8192u + s1 * 16u, Bt + (size_t)r1s * 512 + k0 + k81 * 8);
            CP_COMMIT();
        }

        const uint32_t aB = sbA + buf * 8192u;
        const uint32_t bB = sbB + buf * 8192u;
#pragma unroll
        for (int kk = 0; kk < 2; kk++) {
            uint32_t af[2][4];
            uint32_t bf[8][2];
#pragma unroll
            for (int fm = 0; fm < 2; fm++)
                ldsm_x4(af[fm][0], af[fm][1], af[fm][2], af[fm][3],
                        aB + (aLane + (uint32_t)(kk * 256 + fm * 16)) * 16u);
#pragma unroll
            for (int p = 0; p < 4; p++)
                ldsm_x4(bf[2 * p][0], bf[2 * p][1], bf[2 * p + 1][0], bf[2 * p + 1][1],
                        bB + (bLane + (uint32_t)(kk * 256 + p * 16)) * 16u);
#pragma unroll
            for (int fm = 0; fm < 2; fm++)
#pragma unroll
                for (int fn = 0; fn < 8; fn++)
                    MMA16816(acc[fm][fn], af[fm], bf[fn]);
        }

        if (nxt) CP_WAIT0();
        __syncthreads();
    }

#pragma unroll
    for (int fm = 0; fm < 2; fm++) {
        int r0 = m0 + wm * 32 + fm * 16 + g;
        int r1 = r0 + 8;
        float d0 = (r0 < M) ? dinv[r0] : 0.0f;
        float d1 = (r1 < M) ? dinv[r1] : 0.0f;
#pragma unroll
        for (int fn = 0; fn < 8; fn++) {
            int col = wn * 64 + fn * 8 + c * 2;
            if (r0 < M) {
                __half2 v = __floats2half2_rn(acc[fm][fn][0] * d0, acc[fm][fn][1] * d0);
                *(__half2*)&Hs[(size_t)r0 * 128 + col] = v;
            }
            if (r1 < M) {
                __half2 v = __floats2half2_rn(acc[fm][fn][2] * d1, acc[fm][fn][3] * d1);
                *(__half2*)&Hs[(size_t)r1 * 128 + col] = v;
            }
        }
    }
}

// ---------------------------------------------------------------------------
// pull1 (fp16, 4-way unrolled)
// ---------------------------------------------------------------------------
__global__ void k_pull1_h(const int* __restrict__ rowp, const int* __restrict__ colA,
                          const __half* __restrict__ h16, const float* __restrict__ dinv,
                          const float* __restrict__ bias, __half* __restrict__ agg16,
                          int n, int cbase) {
    int idx = blockIdx.x * blockDim.x + threadIdx.x;
    int dst = idx >> 5;
    int j   = idx & 31;
    if (dst >= n) return;
    const uint2* h2p = (const uint2*)h16;
    const int u = cbase + j;

    float dd = __ldg(&dinv[dst]);
    uint2 sv = h2p[(size_t)dst * 128 + u];
    float2 f0 = __half22float2(*(__half2*)&sv.x), f1 = __half22float2(*(__half2*)&sv.y);
    float4 acc = make_float4(f0.x * dd, f0.y * dd, f1.x * dd, f1.y * dd);

    int e0 = __ldg(&rowp[dst]);
    int e1 = __ldg(&rowp[dst + 1]);
    int e  = e0;
    for (; e + 4 <= e1; e += 4) {
        int s0 = __ldg(&colA[e]);
        int s1 = __ldg(&colA[e + 1]);
        int s2 = __ldg(&colA[e + 2]);
        int s3 = __ldg(&colA[e + 3]);
        float d0 = __ldg(&dinv[s0]);
        float d1 = __ldg(&dinv[s1]);
        float d2 = __ldg(&dinv[s2]);
        float d3 = __ldg(&dinv[s3]);
        uint2 v0 = h2p[(size_t)s0 * 128 + u];
        uint2 v1 = h2p[(size_t)s1 * 128 + u];
        uint2 v2 = h2p[(size_t)s2 * 128 + u];
        uint2 v3 = h2p[(size_t)s3 * 128 + u];
        float2 a0 = __half22float2(*(__half2*)&v0.x), a1 = __half22float2(*(__half2*)&v0.y);
        float2 b0 = __half22float2(*(__half2*)&v1.x), b1 = __half22float2(*(__half2*)&v1.y);
        float2 c0 = __half22float2(*(__half2*)&v2.x), c1 = __half22float2(*(__half2*)&v2.y);
        float2 q0 = __half22float2(*(__half2*)&v3.x), q1 = __half22float2(*(__half2*)&v3.y);
        acc.x += a0.x * d0 + b0.x * d1 + c0.x * d2 + q0.x * d3;
        acc.y += a0.y * d0 + b0.y * d1 + c0.y * d2 + q0.y * d3;
        acc.z += a1.x * d0 + b1.x * d1 + c1.x * d2 + q1.x * d3;
        acc.w += a1.y * d0 + b1.y * d1 + c1.y * d2 + q1.y * d3;
    }
    for (; e < e1; e++) {
        int s = __ldg(&colA[e]);
        float ds = __ldg(&dinv[s]);
        uint2 hv = h2p[(size_t)s * 128 + u];
        float2 g0 = __half22float2(*(__half2*)&hv.x), g1 = __half22float2(*(__half2*)&hv.y);
        acc.x += g0.x * ds; acc.y += g0.y * ds;
        acc.z += g1.x * ds; acc.w += g1.y * ds;
    }

    float4 bb = ((const float4*)bias)[u];
    __half2 o0 = __floats2half2_rn(bb.x + acc.x * dd, bb.y + acc.y * dd);
    __half2 o1 = __floats2half2_rn(bb.z + acc.z * dd, bb.w + acc.w * dd);
    uint2 ov = make_uint2(*(uint32_t*)&o0, *(uint32_t*)&o1);
    __stcs((uint2*)&((uint2*)agg16)[(size_t)dst * 128 + u], ov);
}

// ---------------------------------------------------------------------------
// pull2 (fp16 gather, fp32 out, 4-way unrolled)
// ---------------------------------------------------------------------------
__global__ void k_pull2(const int* __restrict__ rowp, const int* __restrict__ colA,
                        const __half* __restrict__ hs, const float* __restrict__ dinv,
                        const float* __restrict__ bias, float* __restrict__ out, int n) {
    int idx = blockIdx.x * blockDim.x + threadIdx.x;
    int dst = idx >> 5;
    int j   = idx & 31;
    if (dst >= n) return;
    const uint2* h2p = (const uint2*)hs;

    uint2 sv = h2p[(size_t)dst * 32 + j];
    float2 f0 = __half22float2(*(__half2*)&sv.x), f1 = __half22float2(*(__half2*)&sv.y);
    float4 acc = make_float4(f0.x, f0.y, f1.x, f1.y);

    int e0 = __ldg(&rowp[dst]);
    int e1 = __ldg(&rowp[dst + 1]);
    int e  = e0;
    for (; e + 4 <= e1; e += 4) {
        int s0 = __ldg(&colA[e]);
        int s1 = __ldg(&colA[e + 1]);
        int s2 = __ldg(&colA[e + 2]);
        int s3 = __ldg(&colA[e + 3]);
        uint2 v0 = h2p[(size_t)s0 * 32 + j];
        uint2 v1 = h2p[(size_t)s1 * 32 + j];
        uint2 v2 = h2p[(size_t)s2 * 32 + j];
        uint2 v3 = h2p[(size_t)s3 * 32 + j];
        float2 a0 = __half22float2(*(__half2*)&v0.x), a1 = __half22float2(*(__half2*)&v0.y);
        float2 b0 = __half22float2(*(__half2*)&v1.x), b1 = __half22float2(*(__half2*)&v1.y);
        float2 c0 = __half22float2(*(__half2*)&v2.x), c1 = __half22float2(*(__half2*)&v2.y);
        float2 q0 = __half22float2(*(__half2*)&v3.x), q1 = __half22float2(*(__half2*)&v3.y);
        acc.x += a0.x + b0.x + c0.x + q0.x;
        acc.y += a0.y + b0.y + c0.y + q0.y;
        acc.z += a1.x + b1.x + c1.x + q1.x;
        acc.w += a1.y + b1.y + c1.y + q1.y;
    }
    for (; e < e1; e++) {
        int s = __ldg(&colA[e]);
        uint2 hv = h2p[(size_t)s * 32 + j];
        float2 g0 = __half22float2(*(__half2*)&hv.x), g1 = __half22float2(*(__half2*)&hv.y);
        acc.x += g0.x; acc.y += g0.y; acc.z += g1.x; acc.w += g1.y;
    }

    float d = dinv[dst];
    float4 bb = ((const float4*)bias)[j];
    float4 o = make_float4(bb.x + acc.x * d, bb.y + acc.y * d,
                           bb.z + acc.z * d, bb.w + acc.w * d);
    __stcs(&((float4*)out)[(size_t)dst * 32 + j], o);
}

// ---------------------------------------------------------------------------
extern "C" void kernel_launch(void* const* d_in, const int* in_sizes, int n_in,
                              void* d_out, int out_size) {
    const float* x   = (const float*)d_in[0];
    const void*  ei  = d_in[1];
    const float* W1  = (const float*)d_in[3];
    const float* b1  = (const float*)d_in[4];
    const float* W2  = (const float*)d_in[5];
    const float* b2  = (const float*)d_in[6];
    float*       out = (float*)d_out;

    const long long nelem = (long long)in_sizes[1];
    const long long E     = nelem / 2;
    const int dhid        = in_sizes[4];         // 512
    const int dout        = in_sizes[6];         // 128
    const int din         = in_sizes[3] / dhid;  // 512
    const int n           = in_sizes[0] / din;   // 100000

    __half *h16_p, *agg16_p, *wt1_p, *wt2_p, *hs2h_p;
    float *dinv_p;
    int *cnt_p, *rowp_p, *cur_p, *col_p, *bsum_p;
    cudaGetSymbolAddress((void**)&h16_p,   g_h16);
    cudaGetSymbolAddress((void**)&agg16_p, g_agg16);
    cudaGetSymbolAddress((void**)&wt1_p,   g_wt1);
    cudaGetSymbolAddress((void**)&wt2_p,   g_wt2);
    cudaGetSymbolAddress((void**)&hs2h_p,  g_hs2h);
    cudaGetSymbolAddress((void**)&dinv_p,  g_dinv);
    cudaGetSymbolAddress((void**)&cnt_p,   g_cnt);
    cudaGetSymbolAddress((void**)&rowp_p,  g_rowp);
    cudaGetSymbolAddress((void**)&cur_p,   g_cur);
    cudaGetSymbolAddress((void**)&col_p,   g_col);
    cudaGetSymbolAddress((void**)&bsum_p,  g_bsum);

    static bool attr_set = false;
    if (!attr_set) {
        cudaFuncSetAttribute(k_gemm_big, cudaFuncAttributeMaxDynamicSharedMemorySize, G1_SMEM);
        attr_set = true;
    }

    const int eb   = (int)((E + 255) / 256);
    const int nb   = (n + 255) / 256;
    const int nblk = (n + 1023) / 1024;
    const int pull_blocks = (int)(((long long)n * 32 + 255) / 256);
    const dim3 g1grid(1, (n + 127) / 128);

    cudaStream_t s0 = 0;
    cudaStream_t sB = g_sh.ok ? g_sh.s : (cudaStream_t)0;
    const bool fork = g_sh.ok;

    if (fork) {
        cudaEventRecord(g_sh.e0, s0);
        cudaStreamWaitEvent(sB, g_sh.e0, 0);
    }

    // stream0: W1^T, then GEMM1 halves
    {
        dim3 grid(dhid / 32, din / 32), blk(32, 8);
        k_transpose_h<<<grid, blk, 0, s0>>>(W1, wt1_p, din, dhid);        // 1
    }
    k_init<<<nb, 256, 0, sB>>>(ei, nelem, n, cnt_p);                      // 2 (B)
    k_hist<<<eb, 256, 0, sB>>>(ei, E, cnt_p);                             // 3 (B)
    k_gemm_big<<<g1grid, 512, G1_SMEM, s0>>>(x, wt1_p, h16_p, n, 0);      // 4 (profiled)
    if (fork) cudaEventRecord(g_sh.eA, s0);
    k_gemm_big<<<g1grid, 512, G1_SMEM, s0>>>(x, wt1_p, h16_p, n, 256);

    // streamB: CSR build + W2^T
    k_scan_blk<<<nblk, 1024, 0, sB>>>(cnt_p, rowp_p, bsum_p, n);
    k_scan_top<<<1, 1024, 0, sB>>>(bsum_p, nblk);
    k_scan_add<<<(n + 256) / 256, 256, 0, sB>>>(rowp_p, bsum_p, n, nblk);
    k_dinv_cursor<<<nb, 256, 0, sB>>>(cnt_p, rowp_p, dinv_p, cur_p, n);
    k_scatter<<<eb, 256, 0, sB>>>(ei, E, cur_p, col_p);
    {
        dim3 grid(dout / 32, dhid / 32), blk(32, 8);
        k_transpose_h<<<grid, blk, 0, sB>>>(W2, wt2_p, dhid, dout);
    }
    if (fork) cudaEventRecord(g_sh.eCSR, sB);

    // streamB: pull1 chunks 0,1 (need GEMM1a cols 0-255 + CSR)
    if (fork) cudaStreamWaitEvent(sB, g_sh.eA, 0);
    k_pull1_h<<<pull_blocks, 256, 0, sB>>>(rowp_p, col_p, h16_p, dinv_p, b1, agg16_p, n, 0);
    k_pull1_h<<<pull_blocks, 256, 0, sB>>>(rowp_p, col_p, h16_p, dinv_p, b1, agg16_p, n, 32);
    if (fork) cudaEventRecord(g_sh.eB, sB);

    // stream0: pull1 chunks 2,3 (need GEMM1b + CSR)
    if (fork) cudaStreamWaitEvent(s0, g_sh.eCSR, 0);
    k_pull1_h<<<pull_blocks, 256, 0, s0>>>(rowp_p, col_p, h16_p, dinv_p, b1, agg16_p, n, 64);
    k_pull1_h<<<pull_blocks, 256, 0, s0>>>(rowp_p, col_p, h16_p, dinv_p, b1, agg16_p, n, 96);

    // join: GEMM2 needs all agg16 chunks
    if (fork) cudaStreamWaitEvent(s0, g_sh.eB, 0);
    {
        dim3 grid(1, (n + 127) / 128);
        k_gemm2<<<grid, 256, 0, s0>>>(agg16_p, wt2_p, dinv_p, hs2h_p, n);
    }
    k_pull2<<<pull_blocks, 256, 0, s0>>>(rowp_p, col_p, hs2h_p, dinv_p, b2, out, n);

    (void)n_in; (void)out_size;
}

// round 14
// speedup vs baseline: 1.0504x; 1.0504x over previous
#include <cuda_runtime.h>
#include <cuda_fp16.h>
#include <stdint.h>

// ---------------------------------------------------------------------------
// GCN 2-layer, fp16 tensor-core GEMMs (m16n8k16, fp32 accum), fp16 feature
// buffers, CSR pull aggregation. Pipelined two-stream schedule (R12 base):
//   stream0: xcvt -> W1^T -> GEMM1a(N 0-255) -> GEMM1b(N 256-511)
//            -> pull1 c2,c3 -> GEMM2 -> pull2
//   streamB: init -> hist -> scan -> dinv -> scatter -> W2^T
//            -> (after GEMM1a) pull1 c0,c1
// ---------------------------------------------------------------------------

#define MAXN 100352
#define MAXE 1048576

__device__ __half g_xh[(size_t)MAXN * 512];
__device__ __half g_h16[(size_t)MAXN * 512];
__device__ __half g_agg16[(size_t)MAXN * 512];
__device__ __half g_hs2h[(size_t)MAXN * 128];
__device__ __half g_wt1[(size_t)512 * 512];
__device__ __half g_wt2[(size_t)128 * 512];
__device__ float  g_dinv[MAXN];
__device__ int    g_cnt[MAXN];
__device__ int    g_rowp[MAXN + 1];
__device__ int    g_cur[MAXN];
__device__ int    g_col[MAXE];
__device__ int    g_bsum[1025];
__device__ int    g_is64;

// --------- side stream + events, created pre-main (global ctor) ------------
struct StreamHolder {
    cudaStream_t s;
    cudaEvent_t  e0, eA, eB;
    bool ok;
    StreamHolder() {
        ok = (cudaStreamCreateWithFlags(&s, cudaStreamNonBlocking) == cudaSuccess);
        ok = ok && (cudaEventCreateWithFlags(&e0, cudaEventDisableTiming) == cudaSuccess);
        ok = ok && (cudaEventCreateWithFlags(&eA, cudaEventDisableTiming) == cudaSuccess);
        ok = ok && (cudaEventCreateWithFlags(&eB, cudaEventDisableTiming) == cudaSuccess);
        if (!ok) s = 0;
    }
};
static StreamHolder g_sh;

// ------------------------------- helpers -----------------------------------
__device__ __forceinline__ uint32_t smem_u32(const void* p) {
    uint32_t a;
    asm("{ .reg .u64 t; cvta.to.shared.u64 t, %1; cvt.u32.u64 %0, t; }" : "=r"(a) : "l"(p));
    return a;
}
__device__ __forceinline__ void ldsm_x4(uint32_t& r0, uint32_t& r1, uint32_t& r2, uint32_t& r3,
                                        uint32_t addr) {
    asm volatile("ldmatrix.sync.aligned.m8n8.x4.shared.b16 {%0,%1,%2,%3}, [%4];"
                 : "=r"(r0), "=r"(r1), "=r"(r2), "=r"(r3) : "r"(addr));
}
__device__ __forceinline__ void cp_async16(uint32_t dst, const void* src) {
    asm volatile("cp.async.ca.shared.global [%0], [%1], 16;" :: "r"(dst), "l"(src) : "memory");
}
#define CP_COMMIT() asm volatile("cp.async.commit_group;" ::: "memory")
#define CP_WAIT0()  asm volatile("cp.async.wait_group 0;" ::: "memory")
#define CP_WAIT1()  asm volatile("cp.async.wait_group 1;" ::: "memory")

#define MMA16816(acc, af, bf)                                                  \
    asm volatile(                                                              \
        "mma.sync.aligned.m16n8k16.row.col.f32.f16.f16.f32 "                   \
        "{%0,%1,%2,%3}, {%4,%5,%6,%7}, {%8,%9}, {%0,%1,%2,%3};"                \
        : "+f"((acc)[0]), "+f"((acc)[1]), "+f"((acc)[2]), "+f"((acc)[3])       \
        : "r"((af)[0]), "r"((af)[1]), "r"((af)[2]), "r"((af)[3]),              \
          "r"((bf)[0]), "r"((bf)[1]))

__device__ __forceinline__ long long edge_at(const void* ei, long long idx, int is64) {
    if (is64) return ((const long long*)ei)[idx];
    return (long long)((const int*)ei)[idx];
}

// ---------------------------------------------------------------------------
__global__ void k_xcvt(const float* __restrict__ x, int n, __half* __restrict__ xh) {
    int gid = blockIdx.x * blockDim.x + threadIdx.x;
    const int total = MAXN * 64;
    if (gid >= total) return;
    int row = gid >> 6, u = gid & 63;
    uint4 o;
    if (row < n) {
        const float4 v0 = *(const float4*)&x[(size_t)row * 512 + u * 8];
        const float4 v1 = *(const float4*)&x[(size_t)row * 512 + u * 8 + 4];
        __half2 h0 = __floats2half2_rn(v0.x, v0.y);
        __half2 h1 = __floats2half2_rn(v0.z, v0.w);
        __half2 h2 = __floats2half2_rn(v1.x, v1.y);
        __half2 h3 = __floats2half2_rn(v1.z, v1.w);
        o = make_uint4(*(uint32_t*)&h0, *(uint32_t*)&h1, *(uint32_t*)&h2, *(uint32_t*)&h3);
    } else {
        o = make_uint4(0, 0, 0, 0);
    }
    *(uint4*)&xh[(size_t)gid * 8] = o;
}

__global__ void k_init(const void* ei, long long nelem, int n, int* cnt) {
    int i = blockIdx.x * blockDim.x + threadIdx.x;
    if (i < n) cnt[i] = 0;
    if (blockIdx.x == 0 && threadIdx.x == 0) {
        const long long* p = (const long long*)ei;
        long long m = 64;
        if (m > nelem / 2) m = nelem / 2;
        int is64 = 1;
        for (long long j = 0; j < m; j++) {
            long long v = p[j];
            if (v < 0 || v >= (long long)n) { is64 = 0; break; }
        }
        g_is64 = is64;
    }
}

__global__ void k_transpose_h(const float* __restrict__ W, __half* __restrict__ Wt, int K, int N) {
    __shared__ float tile[32][33];
    int k0 = blockIdx.y * 32, n0 = blockIdx.x * 32;
    int tx = threadIdx.x, ty = threadIdx.y;  // 32 x 8
    for (int j = 0; j < 32; j += 8)
        tile[ty + j][tx] = W[(size_t)(k0 + ty + j) * N + n0 + tx];
    __syncthreads();
    for (int j = 0; j < 32; j += 8)
        Wt[(size_t)(n0 + ty + j) * K + k0 + tx] = __float2half_rn(tile[tx][ty + j]);
}

__global__ void k_hist(const void* __restrict__ ei, long long E, int* __restrict__ cnt) {
    long long i = (long long)blockIdx.x * blockDim.x + threadIdx.x;
    if (i >= E) return;
    int d = (int)edge_at(ei, E + i, g_is64);
    atomicAdd(&cnt[d], 1);
}

__global__ void k_scan_blk(const int* __restrict__ cnt, int* __restrict__ rowp,
                           int* __restrict__ bsum, int n) {
    __shared__ int warpsum[32];
    const int t = threadIdx.x, lane = t & 31, w = t >> 5;
    int i = blockIdx.x * 1024 + t;
    int v = (i < n) ? cnt[i] : 0;
    int x = v;
#pragma unroll
    for (int off = 1; off < 32; off <<= 1) {
        int y = __shfl_up_sync(0xFFFFFFFFu, x, off);
        if (lane >= off) x += y;
    }
    if (lane == 31) warpsum[w] = x;
    __syncthreads();
    if (w == 0) {
        int s = warpsum[lane];
#pragma unroll
        for (int off = 1; off < 32; off <<= 1) {
            int y = __shfl_up_sync(0xFFFFFFFFu, s, off);
            if (lane >= off) s += y;
        }
        warpsum[lane] = s;
    }
    __syncthreads();
    int wpre = (w > 0) ? warpsum[w - 1] : 0;
    if (i < n) rowp[i] = x - v + wpre;
    if (t == 1023) bsum[blockIdx.x] = wpre + x;
}

__global__ void k_scan_top(int* __restrict__ bsum, int nb) {
    __shared__ int warpsum[32];
    const int t = threadIdx.x, lane = t & 31, w = t >> 5;
    int v = (t < nb) ? bsum[t] : 0;
    int x = v;
#pragma unroll
    for (int off = 1; off < 32; off <<= 1) {
        int y = __shfl_up_sync(0xFFFFFFFFu, x, off);
        if (lane >= off) x += y;
    }
    if (lane == 31) warpsum[w] = x;
    __syncthreads();
    if (w == 0) {
        int s = warpsum[lane];
#pragma unroll
        for (int off = 1; off < 32; off <<= 1) {
            int y = __shfl_up_sync(0xFFFFFFFFu, s, off);
            if (lane >= off) s += y;
        }
        warpsum[lane] = s;
    }
    __syncthreads();
    int wpre = (w > 0) ? warpsum[w - 1] : 0;
    if (t < nb) bsum[t] = x - v + wpre;
    if (t == 1023) bsum[nb] = warpsum[31];
}

__global__ void k_scan_add(int* __restrict__ rowp, const int* __restrict__ bsum, int n, int nb) {
    int i = blockIdx.x * blockDim.x + threadIdx.x;
    if (i < n) rowp[i] += bsum[i >> 10];
    if (i == n) rowp[n] = bsum[nb];
}

__global__ void k_dinv_cursor(const int* __restrict__ cnt, const int* __restrict__ rowp,
                              float* __restrict__ dinv, int* __restrict__ cur, int n) {
    int i = blockIdx.x * blockDim.x + threadIdx.x;
    if (i >= n) return;
    dinv[i] = rsqrtf((float)cnt[i] + 1.0f);
    cur[i]  = rowp[i];
}

__global__ void k_scatter(const void* __restrict__ ei, long long E,
                          int* __restrict__ cur, int* __restrict__ colA) {
    long long i = (long long)blockIdx.x * blockDim.x + threadIdx.x;
    if (i >= E) return;
    int is64 = g_is64;
    int s = (int)edge_at(ei, i, is64);
    int d = (int)edge_at(ei, E + i, is64);
    int pos = atomicAdd(&cur[d], 1);
    colA[pos] = s;
}

// ---------------------------------------------------------------------------
// GEMM1 (N-half launch): H16[M, ncol0:ncol0+256] = A16[M,512] @ Wt[n0:,512]^T
// Block 128x256, 512 threads (16 warps 4x4), warp tile 32x64, BK=32,
// 3-stage cp.async (A fp16 via cp.async -- proven R12 profile).
// ---------------------------------------------------------------------------
#define G1_SMEM (3 * (8192 + 16384))

__global__ __launch_bounds__(512, 1)
void k_gemm_big(const __half* __restrict__ A, const __half* __restrict__ Bt,
                __half* __restrict__ H, int ncol0)
{
    extern __shared__ __align__(16) char smem[];
    const uint32_t sbA = smem_u32(smem);
    const uint32_t sbB = sbA + 3 * 8192;

    const int t   = threadIdx.x;
    const int L   = t & 31;
    const int wid = t >> 5;
    const int wm  = wid >> 2;
    const int wn  = wid & 3;
    const int g   = L >> 2;
    const int c   = L & 3;
    const int m0  = blockIdx.y * 128;
    const int n0  = ncol0;

    const uint32_t aLane = ((uint32_t)((L >> 4) & 1)) * 128u
                         + (uint32_t)(wm * 32) + (uint32_t)(L & 7) + ((uint32_t)((L >> 3) & 1)) * 8u;
    const uint32_t bLane = ((uint32_t)((L >> 3) & 1)) * 256u
                         + (uint32_t)(wn * 64) + (uint32_t)(L & 7) + ((uint32_t)((L >> 4) & 1)) * 8u;

    const int a_row = t & 127, a_k8 = t >> 7;
    const int b_r0  = t & 255, b_k0 = t >> 8;
    const int b_r1  = b_r0,    b_k1 = b_k0 + 2;

    float acc[2][8][4];
#pragma unroll
    for (int i = 0; i < 2; i++)
#pragma unroll
        for (int j = 0; j < 8; j++)
#pragma unroll
            for (int q = 0; q < 4; q++) acc[i][j][q] = 0.0f;

    auto issue = [&](int kt) {
        const int stg = kt % 3;
        const int k0 = kt * 32;
        cp_async16(sbA + stg * 8192u + (uint32_t)t * 16u,
                   A + (size_t)(m0 + a_row) * 512 + k0 + a_k8 * 8);
        uint32_t bbase = sbB + stg * 16384u;
        cp_async16(bbase + (uint32_t)t * 16u,
                   Bt + (size_t)(n0 + b_r0) * 512 + k0 + b_k0 * 8);
        cp_async16(bbase + (uint32_t)(t + 512) * 16u,
                   Bt + (size_t)(n0 + b_r1) * 512 + k0 + b_k1 * 8);
        CP_COMMIT();
    };

    issue(0);
    issue(1);

    for (int kt = 0; kt < 16; kt++) {
        if (kt + 1 < 16) { CP_WAIT1(); } else { CP_WAIT0(); }
        __syncthreads();

        const int stg = kt % 3;
        const uint32_t aB = sbA + stg * 8192u;
        const uint32_t bB = sbB + stg * 16384u;
#pragma unroll
        for (int kk = 0; kk < 2; kk++) {
            uint32_t af[2][4];
            uint32_t bf[8][2];
#pragma unroll
            for (int fm = 0; fm < 2; fm++)
                ldsm_x4(af[fm][0], af[fm][1], af[fm][2], af[fm][3],
                        aB + (aLane + (uint32_t)(kk * 256 + fm * 16)) * 16u);
#pragma unroll
            for (int p = 0; p < 4; p++)
                ldsm_x4(bf[2 * p][0], bf[2 * p][1], bf[2 * p + 1][0], bf[2 * p + 1][1],
                        bB + (bLane + (uint32_t)(kk * 512 + p * 16)) * 16u);
#pragma unroll
            for (int fm = 0; fm < 2; fm++)
#pragma unroll
                for (int fn = 0; fn < 8; fn++)
                    MMA16816(acc[fm][fn], af[fm], bf[fn]);
        }

        if (kt + 2 < 16) issue(kt + 2);
    }

    // epilogue: raw fp16 store (rows zero-padded in xh -> no M guard)
#pragma unroll
    for (int fm = 0; fm < 2; fm++) {
        int r0 = m0 + wm * 32 + fm * 16 + g;
        int r1 = r0 + 8;
#pragma unroll
        for (int fn = 0; fn < 8; fn++) {
            int col = n0 + wn * 64 + fn * 8 + c * 2;
            __half2 v0 = __floats2half2_rn(acc[fm][fn][0], acc[fm][fn][1]);
            __half2 v1 = __floats2half2_rn(acc[fm][fn][2], acc[fm][fn][3]);
            *(__half2*)&H[(size_t)r0 * 512 + col] = v0;
            *(__half2*)&H[(size_t)r1 * 512 + col] = v1;
        }
    }
}

// ---------------------------------------------------------------------------
// GEMM2: Hs2h[M,128] = (A16[M,512] @ Wt2[128,512]^T) * dinv[row]  (fp16 out)
// ---------------------------------------------------------------------------
__global__ __launch_bounds__(256, 2)
void k_gemm2(const __half* __restrict__ A, const __half* __restrict__ Bt,
             const float* __restrict__ dinv, __half* __restrict__ Hs, int M)
{
    __shared__ __align__(16) char smem[32768];
    const uint32_t sbA = smem_u32(smem);
    const uint32_t sbB = sbA + 16384;

    const int t   = threadIdx.x;
    const int L   = t & 31;
    const int wid = t >> 5;
    const int wm  = wid >> 1;
    const int wn  = wid & 1;
    const int g   = L >> 2;
    const int c   = L & 3;
    const int m0  = blockIdx.y * 128;

    const uint32_t aLane = ((uint32_t)((L >> 4) & 1)) * 128u
                         + (uint32_t)(wm * 32) + (uint32_t)(L & 7) + ((uint32_t)((L >> 3) & 1)) * 8u;
    const uint32_t bLane = ((uint32_t)((L >> 3) & 1)) * 128u
                         + (uint32_t)(wn * 64) + (uint32_t)(L & 7) + ((uint32_t)((L >> 4) & 1)) * 8u;

    const int s0 = t, s1 = t + 256;
    const int r0s = s0 & 127, k80 = s0 >> 7;
    const int r1s = s1 & 127, k81 = s1 >> 7;
    const bool m0v = (m0 + r0s) < M, m1v = (m0 + r1s) < M;
    const int ar0 = m0v ? (m0 + r0s) : 0;
    const int ar1 = m1v ? (m0 + r1s) : 0;

    float acc[2][8][4];
#pragma unroll
    for (int i = 0; i < 2; i++)
#pragma unroll
        for (int j = 0; j < 8; j++)
#pragma unroll
            for (int q = 0; q < 4; q++) acc[i][j][q] = 0.0f;

    {
        cp_async16(sbA + s0 * 16u, A + (size_t)ar0 * 512 + k80 * 8);
        cp_async16(sbA + s1 * 16u, A + (size_t)ar1 * 512 + k81 * 8);
        cp_async16(sbB + s0 * 16u, Bt + (size_t)r0s * 512 + k80 * 8);
        cp_async16(sbB + s1 * 16u, Bt + (size_t)r1s * 512 + k81 * 8);
        CP_COMMIT();
        CP_WAIT0();
    }
    __syncthreads();

    for (int kt = 0; kt < 16; kt++) {
        const int buf  = kt & 1;
        const int nbuf = 1 - buf;
        const bool nxt = (kt + 1) < 16;

        if (nxt) {
            const int k0 = (kt + 1) * 32;
            cp_async16(sbA + nbuf * 8192u + s0 * 16u, A + (size_t)ar0 * 512 + k0 + k80 * 8);
            cp_async16(sbA + nbuf * 8192u + s1 * 16u, A + (size_t)ar1 * 512 + k0 + k81 * 8);
            cp_async16(sbB + nbuf * 8192u + s0 * 16u, Bt + (size_t)r0s * 512 + k0 + k80 * 8);
            cp_async16(sbB + nbuf * 8192u + s1 * 16u, Bt + (size_t)r1s * 512 + k0 + k81 * 8);
            CP_COMMIT();
        }

        const uint32_t aB = sbA + buf * 8192u;
        const uint32_t bB = sbB + buf * 8192u;
#pragma unroll
        for (int kk = 0; kk < 2; kk++) {
            uint32_t af[2][4];
            uint32_t bf[8][2];
#pragma unroll
            for (int fm = 0; fm < 2; fm++)
                ldsm_x4(af[fm][0], af[fm][1], af[fm][2], af[fm][3],
                        aB + (aLane + (uint32_t)(kk * 256 + fm * 16)) * 16u);
#pragma unroll
            for (int p = 0; p < 4; p++)
                ldsm_x4(bf[2 * p][0], bf[2 * p][1], bf[2 * p + 1][0], bf[2 * p + 1][1],
                        bB + (bLane + (uint32_t)(kk * 256 + p * 16)) * 16u);
#pragma unroll
            for (int fm = 0; fm < 2; fm++)
#pragma unroll
                for (int fn = 0; fn < 8; fn++)
                    MMA16816(acc[fm][fn], af[fm], bf[fn]);
        }

        if (nxt) CP_WAIT0();
        __syncthreads();
    }

#pragma unroll
    for (int fm = 0; fm < 2; fm++) {
        int r0 = m0 + wm * 32 + fm * 16 + g;
        int r1 = r0 + 8;
        float d0 = (r0 < M) ? dinv[r0] : 0.0f;
        float d1 = (r1 < M) ? dinv[r1] : 0.0f;
#pragma unroll
        for (int fn = 0; fn < 8; fn++) {
            int col = wn * 64 + fn * 8 + c * 2;
            if (r0 < M) {
                __half2 v = __floats2half2_rn(acc[fm][fn][0] * d0, acc[fm][fn][1] * d0);
                *(__half2*)&Hs[(size_t)r0 * 128 + col] = v;
            }
            if (r1 < M) {
                __half2 v = __floats2half2_rn(acc[fm][fn][2] * d1, acc[fm][fn][3] * d1);
                *(__half2*)&Hs[(size_t)r1 * 128 + col] = v;
            }
        }
    }
}

// ---------------------------------------------------------------------------
// pull1 (fp16, 4-way unrolled)
// ---------------------------------------------------------------------------
__global__ void k_pull1_h(const int* __restrict__ rowp, const int* __restrict__ colA,
                          const __half* __restrict__ h16, const float* __restrict__ dinv,
                          const float* __restrict__ bias, __half* __restrict__ agg16,
                          int n, int cbase) {
    int idx = blockIdx.x * blockDim.x + threadIdx.x;
    int dst = idx >> 5;
    int j   = idx & 31;
    if (dst >= n) return;
    const uint2* h2p = (const uint2*)h16;
    const int u = cbase + j;

    float dd = __ldg(&dinv[dst]);
    uint2 sv = h2p[(size_t)dst * 128 + u];
    float2 f0 = __half22float2(*(__half2*)&sv.x), f1 = __half22float2(*(__half2*)&sv.y);
    float4 acc = make_float4(f0.x * dd, f0.y * dd, f1.x * dd, f1.y * dd);

    int e0 = __ldg(&rowp[dst]);
    int e1 = __ldg(&rowp[dst + 1]);
    int e  = e0;
    for (; e + 4 <= e1; e += 4) {
        int s0 = __ldg(&colA[e]);
        int s1 = __ldg(&colA[e + 1]);
        int s2 = __ldg(&colA[e + 2]);
        int s3 = __ldg(&colA[e + 3]);
        float d0 = __ldg(&dinv[s0]);
        float d1 = __ldg(&dinv[s1]);
        float d2 = __ldg(&dinv[s2]);
        float d3 = __ldg(&dinv[s3]);
        uint2 v0 = h2p[(size_t)s0 * 128 + u];
        uint2 v1 = h2p[(size_t)s1 * 128 + u];
        uint2 v2 = h2p[(size_t)s2 * 128 + u];
        uint2 v3 = h2p[(size_t)s3 * 128 + u];
        float2 a0 = __half22float2(*(__half2*)&v0.x), a1 = __half22float2(*(__half2*)&v0.y);
        float2 b0 = __half22float2(*(__half2*)&v1.x), b1 = __half22float2(*(__half2*)&v1.y);
        float2 c0 = __half22float2(*(__half2*)&v2.x), c1 = __half22float2(*(__half2*)&v2.y);
        float2 q0 = __half22float2(*(__half2*)&v3.x), q1 = __half22float2(*(__half2*)&v3.y);
        acc.x += a0.x * d0 + b0.x * d1 + c0.x * d2 + q0.x * d3;
        acc.y += a0.y * d0 + b0.y * d1 + c0.y * d2 + q0.y * d3;
        acc.z += a1.x * d0 + b1.x * d1 + c1.x * d2 + q1.x * d3;
        acc.w += a1.y * d0 + b1.y * d1 + c1.y * d2 + q1.y * d3;
    }
    for (; e < e1; e++) {
        int s = __ldg(&colA[e]);
        float ds = __ldg(&dinv[s]);
        uint2 hv = h2p[(size_t)s * 128 + u];
        float2 g0 = __half22float2(*(__half2*)&hv.x), g1 = __half22float2(*(__half2*)&hv.y);
        acc.x += g0.x * ds; acc.y += g0.y * ds;
        acc.z += g1.x * ds; acc.w += g1.y * ds;
    }

    float4 bb = ((const float4*)bias)[u];
    __half2 o0 = __floats2half2_rn(bb.x + acc.x * dd, bb.y + acc.y * dd);
    __half2 o1 = __floats2half2_rn(bb.z + acc.z * dd, bb.w + acc.w * dd);
    uint2 ov = make_uint2(*(uint32_t*)&o0, *(uint32_t*)&o1);
    __stcs((uint2*)&((uint2*)agg16)[(size_t)dst * 128 + u], ov);
}

// ---------------------------------------------------------------------------
// pull2 (fp16 gather, fp32 out, 4-way unrolled)
// ---------------------------------------------------------------------------
__global__ void k_pull2(const int* __restrict__ rowp, const int* __restrict__ colA,
                        const __half* __restrict__ hs, const float* __restrict__ dinv,
                        const float* __restrict__ bias, float* __restrict__ out, int n) {
    int idx = blockIdx.x * blockDim.x + threadIdx.x;
    int dst = idx >> 5;
    int j   = idx & 31;
    if (dst >= n) return;
    const uint2* h2p = (const uint2*)hs;

    uint2 sv = h2p[(size_t)dst * 32 + j];
    float2 f0 = __half22float2(*(__half2*)&sv.x), f1 = __half22float2(*(__half2*)&sv.y);
    float4 acc = make_float4(f0.x, f0.y, f1.x, f1.y);

    int e0 = __ldg(&rowp[dst]);
    int e1 = __ldg(&rowp[dst + 1]);
    int e  = e0;
    for (; e + 4 <= e1; e += 4) {
        int s0 = __ldg(&colA[e]);
        int s1 = __ldg(&colA[e + 1]);
        int s2 = __ldg(&colA[e + 2]);
        int s3 = __ldg(&colA[e + 3]);
        uint2 v0 = h2p[(size_t)s0 * 32 + j];
        uint2 v1 = h2p[(size_t)s1 * 32 + j];
        uint2 v2 = h2p[(size_t)s2 * 32 + j];
        uint2 v3 = h2p[(size_t)s3 * 32 + j];
        float2 a0 = __half22float2(*(__half2*)&v0.x), a1 = __half22float2(*(__half2*)&v0.y);
        float2 b0 = __half22float2(*(__half2*)&v1.x), b1 = __half22float2(*(__half2*)&v1.y);
        float2 c0 = __half22float2(*(__half2*)&v2.x), c1 = __half22float2(*(__half2*)&v2.y);
        float2 q0 = __half22float2(*(__half2*)&v3.x), q1 = __half22float2(*(__half2*)&v3.y);
        acc.x += a0.x + b0.x + c0.x + q0.x;
        acc.y += a0.y + b0.y + c0.y + q0.y;
        acc.z += a1.x + b1.x + c1.x + q1.x;
        acc.w += a1.y + b1.y + c1.y + q1.y;
    }
    for (; e < e1; e++) {
        int s = __ldg(&colA[e]);
        uint2 hv = h2p[(size_t)s * 32 + j];
        float2 g0 = __half22float2(*(__half2*)&hv.x), g1 = __half22float2(*(__half2*)&hv.y);
        acc.x += g0.x; acc.y += g0.y; acc.z += g1.x; acc.w += g1.y;
    }

    float d = dinv[dst];
    float4 bb = ((const float4*)bias)[j];
    float4 o = make_float4(bb.x + acc.x * d, bb.y + acc.y * d,
                           bb.z + acc.z * d, bb.w + acc.w * d);
    __stcs(&((float4*)out)[(size_t)dst * 32 + j], o);
}

// ---------------------------------------------------------------------------
extern "C" void kernel_launch(void* const* d_in, const int* in_sizes, int n_in,
                              void* d_out, int out_size) {
    const float* x   = (const float*)d_in[0];
    const void*  ei  = d_in[1];
    const float* W1  = (const float*)d_in[3];
    const float* b1  = (const float*)d_in[4];
    const float* W2  = (const float*)d_in[5];
    const float* b2  = (const float*)d_in[6];
    float*       out = (float*)d_out;

    const long long nelem = (long long)in_sizes[1];
    const long long E     = nelem / 2;
    const int dhid        = in_sizes[4];         // 512
    const int dout        = in_sizes[6];         // 128
    const int din         = in_sizes[3] / dhid;  // 512
    const int n           = in_sizes[0] / din;   // 100000

    __half *xh_p, *h16_p, *agg16_p, *wt1_p, *wt2_p, *hs2h_p;
    float *dinv_p;
    int *cnt_p, *rowp_p, *cur_p, *col_p, *bsum_p;
    cudaGetSymbolAddress((void**)&xh_p,    g_xh);
    cudaGetSymbolAddress((void**)&h16_p,   g_h16);
    cudaGetSymbolAddress((void**)&agg16_p, g_agg16);
    cudaGetSymbolAddress((void**)&wt1_p,   g_wt1);
    cudaGetSymbolAddress((void**)&wt2_p,   g_wt2);
    cudaGetSymbolAddress((void**)&hs2h_p,  g_hs2h);
    cudaGetSymbolAddress((void**)&dinv_p,  g_dinv);
    cudaGetSymbolAddress((void**)&cnt_p,   g_cnt);
    cudaGetSymbolAddress((void**)&rowp_p,  g_rowp);
    cudaGetSymbolAddress((void**)&cur_p,   g_cur);
    cudaGetSymbolAddress((void**)&col_p,   g_col);
    cudaGetSymbolAddress((void**)&bsum_p,  g_bsum);

    static bool attr_set = false;
    if (!attr_set) {
        cudaFuncSetAttribute(k_gemm_big, cudaFuncAttributeMaxDynamicSharedMemorySize, G1_SMEM);
        attr_set = true;
    }

    const int eb   = (int)((E + 255) / 256);
    const int nb   = (n + 255) / 256;
    const int nblk = (n + 1023) / 1024;
    const int pull_blocks = (int)(((long long)n * 32 + 255) / 256);
    const dim3 g1grid(1, (n + 127) / 128);

    cudaStream_t s0 = 0;
    cudaStream_t sB = g_sh.ok ? g_sh.s : (cudaStream_t)0;
    const bool fork = g_sh.ok;

    if (fork) {
        cudaEventRecord(g_sh.e0, s0);
        cudaStreamWaitEvent(sB, g_sh.e0, 0);
    }

    // stream0: xcvt -> W1^T -> GEMM1a -> GEMM1b
    k_xcvt<<<(MAXN * 64 + 255) / 256, 256, 0, s0>>>(x, n, xh_p);          // 1
    {
        dim3 grid(dhid / 32, din / 32), blk(32, 8);
        k_transpose_h<<<grid, blk, 0, s0>>>(W1, wt1_p, din, dhid);        // 2
    }
    k_init<<<nb, 256, 0, sB>>>(ei, nelem, n, cnt_p);                      // 3 (B)
    k_gemm_big<<<g1grid, 512, G1_SMEM, s0>>>(xh_p, wt1_p, h16_p, 0);      // 4 (profiled)
    if (fork) cudaEventRecord(g_sh.eA, s0);
    k_gemm_big<<<g1grid, 512, G1_SMEM, s0>>>(xh_p, wt1_p, h16_p, 256);

    // streamB: CSR build + W2^T
    k_hist<<<eb, 256, 0, sB>>>(ei, E, cnt_p);
    k_scan_blk<<<nblk, 1024, 0, sB>>>(cnt_p, rowp_p, bsum_p, n);
    k_scan_top<<<1, 1024, 0, sB>>>(bsum_p, nblk);
    k_scan_add<<<(n + 256) / 256, 256, 0, sB>>>(rowp_p, bsum_p, n, nblk);
    k_dinv_cursor<<<nb, 256, 0, sB>>>(cnt_p, rowp_p, dinv_p, cur_p, n);
    k_scatter<<<eb, 256, 0, sB>>>(ei, E, cur_p, col_p);
    {
        dim3 grid(dout / 32, dhid / 32), blk(32, 8);
        k_transpose_h<<<grid, blk, 0, sB>>>(W2, wt2_p, dhid, dout);
    }

    // streamB: pull1 chunks 0,1 (cols 0-255; CSR already sequenced on sB)
    if (fork) cudaStreamWaitEvent(sB, g_sh.eA, 0);
    k_pull1_h<<<pull_blocks, 256, 0, sB>>>(rowp_p, col_p, h16_p, dinv_p, b1, agg16_p, n, 0);
    k_pull1_h<<<pull_blocks, 256, 0, sB>>>(rowp_p, col_p, h16_p, dinv_p, b1, agg16_p, n, 32);
    if (fork) cudaEventRecord(g_sh.eB, sB);

    // stream0: pull1 chunks 2,3 (need GEMM1b on s0 + CSR from sB)
    if (fork) cudaStreamWaitEvent(s0, g_sh.eB, 0);  // eB also implies CSR done
    k_pull1_h<<<pull_blocks, 256, 0, s0>>>(rowp_p, col_p, h16_p, dinv_p, b1, agg16_p, n, 64);
    k_pull1_h<<<pull_blocks, 256, 0, s0>>>(rowp_p, col_p, h16_p, dinv_p, b1, agg16_p, n, 96);

    // GEMM2 + pull2 (all agg16 ready: c0,c1 before eB, c2,c3 on s0)
    {
        dim3 grid(1, (n + 127) / 128);
        k_gemm2<<<grid, 256, 0, s0>>>(agg16_p, wt2_p, dinv_p, hs2h_p, n);
    }
    k_pull2<<<pull_blocks, 256, 0, s0>>>(rowp_p, col_p, hs2h_p, dinv_p, b2, out, n);

    (void)n_in; (void)out_size;
}

// round 15
// speedup vs baseline: 1.2717x; 1.2107x over previous
#include <cuda_runtime.h>
#include <cuda_fp16.h>
#include <stdint.h>

// ---------------------------------------------------------------------------
// GCN 2-layer, reassociated:  out = A2h(A2h(X W1 W2)) + A2h(b1 W2) + b2
//   h16 = X @ W1^T                      (fp16, GEMM1)
//   Ps  = (h16 @ W2^T) * dinv[row]      (fp16, GEMMP -- 128-wide)
//   u   = dinv^2 (Ps_self + sum Ps[s]) + dinv*c     (pullA, fp16, c = b1 W2)
//   out = dinv (u_self + sum u[s]) + b2             (pullB, fp32)
// Pulls gather from 25.6 MB L2-resident arrays (128-wide).
// Two streams: CSR build + W2^T + c hidden under GEMM1.
// ---------------------------------------------------------------------------

#define MAXN 100352
#define MAXE 1048576

__device__ __half g_xh[(size_t)MAXN * 512];
__device__ __half g_h16[(size_t)MAXN * 512];
__device__ __half g_ps[(size_t)MAXN * 128];
__device__ __half g_u[(size_t)MAXN * 128];
__device__ __half g_wt1[(size_t)512 * 512];
__device__ __half g_wt2[(size_t)128 * 512];
__device__ float  g_c[128];
__device__ float  g_dinv[MAXN];
__device__ int    g_cnt[MAXN];
__device__ int    g_rowp[MAXN + 1];
__device__ int    g_cur[MAXN];
__device__ int    g_col[MAXE];
__device__ int    g_bsum[1025];
__device__ int    g_is64;

// --------- side stream + events, created pre-main (global ctor) ------------
struct StreamHolder {
    cudaStream_t s;
    cudaEvent_t  e0, eB;
    bool ok;
    StreamHolder() {
        ok = (cudaStreamCreateWithFlags(&s, cudaStreamNonBlocking) == cudaSuccess);
        ok = ok && (cudaEventCreateWithFlags(&e0, cudaEventDisableTiming) == cudaSuccess);
        ok = ok && (cudaEventCreateWithFlags(&eB, cudaEventDisableTiming) == cudaSuccess);
        if (!ok) s = 0;
    }
};
static StreamHolder g_sh;

// ------------------------------- helpers -----------------------------------
__device__ __forceinline__ uint32_t smem_u32(const void* p) {
    uint32_t a;
    asm("{ .reg .u64 t; cvta.to.shared.u64 t, %1; cvt.u32.u64 %0, t; }" : "=r"(a) : "l"(p));
    return a;
}
__device__ __forceinline__ void ldsm_x4(uint32_t& r0, uint32_t& r1, uint32_t& r2, uint32_t& r3,
                                        uint32_t addr) {
    asm volatile("ldmatrix.sync.aligned.m8n8.x4.shared.b16 {%0,%1,%2,%3}, [%4];"
                 : "=r"(r0), "=r"(r1), "=r"(r2), "=r"(r3) : "r"(addr));
}
__device__ __forceinline__ void cp_async16(uint32_t dst, const void* src) {
    asm volatile("cp.async.ca.shared.global [%0], [%1], 16;" :: "r"(dst), "l"(src) : "memory");
}
#define CP_COMMIT() asm volatile("cp.async.commit_group;" ::: "memory")
#define CP_WAIT0()  asm volatile("cp.async.wait_group 0;" ::: "memory")
#define CP_WAIT1()  asm volatile("cp.async.wait_group 1;" ::: "memory")

#define MMA16816(acc, af, bf)                                                  \
    asm volatile(                                                              \
        "mma.sync.aligned.m16n8k16.row.col.f32.f16.f16.f32 "                   \
        "{%0,%1,%2,%3}, {%4,%5,%6,%7}, {%8,%9}, {%0,%1,%2,%3};"                \
        : "+f"((acc)[0]), "+f"((acc)[1]), "+f"((acc)[2]), "+f"((acc)[3])       \
        : "r"((af)[0]), "r"((af)[1]), "r"((af)[2]), "r"((af)[3]),              \
          "r"((bf)[0]), "r"((bf)[1]))

__device__ __forceinline__ long long edge_at(const void* ei, long long idx, int is64) {
    if (is64) return ((const long long*)ei)[idx];
    return (long long)((const int*)ei)[idx];
}

// ---------------------------------------------------------------------------
__global__ void k_xcvt(const float* __restrict__ x, int n, __half* __restrict__ xh) {
    int gid = blockIdx.x * blockDim.x + threadIdx.x;
    const int total = MAXN * 64;
    if (gid >= total) return;
    int row = gid >> 6, u = gid & 63;
    uint4 o;
    if (row < n) {
        const float4 v0 = *(const float4*)&x[(size_t)row * 512 + u * 8];
        const float4 v1 = *(const float4*)&x[(size_t)row * 512 + u * 8 + 4];
        __half2 h0 = __floats2half2_rn(v0.x, v0.y);
        __half2 h1 = __floats2half2_rn(v0.z, v0.w);
        __half2 h2 = __floats2half2_rn(v1.x, v1.y);
        __half2 h3 = __floats2half2_rn(v1.z, v1.w);
        o = make_uint4(*(uint32_t*)&h0, *(uint32_t*)&h1, *(uint32_t*)&h2, *(uint32_t*)&h3);
    } else {
        o = make_uint4(0, 0, 0, 0);
    }
    *(uint4*)&xh[(size_t)gid * 8] = o;
}

__global__ void k_init(const void* ei, long long nelem, int n, int* cnt) {
    int i = blockIdx.x * blockDim.x + threadIdx.x;
    if (i < n) cnt[i] = 0;
    if (blockIdx.x == 0 && threadIdx.x == 0) {
        const long long* p = (const long long*)ei;
        long long m = 64;
        if (m > nelem / 2) m = nelem / 2;
        int is64 = 1;
        for (long long j = 0; j < m; j++) {
            long long v = p[j];
            if (v < 0 || v >= (long long)n) { is64 = 0; break; }
        }
        g_is64 = is64;
    }
}

__global__ void k_transpose_h(const float* __restrict__ W, __half* __restrict__ Wt, int K, int N) {
    __shared__ float tile[32][33];
    int k0 = blockIdx.y * 32, n0 = blockIdx.x * 32;
    int tx = threadIdx.x, ty = threadIdx.y;  // 32 x 8
    for (int j = 0; j < 32; j += 8)
        tile[ty + j][tx] = W[(size_t)(k0 + ty + j) * N + n0 + tx];
    __syncthreads();
    for (int j = 0; j < 32; j += 8)
        Wt[(size_t)(n0 + ty + j) * K + k0 + tx] = __float2half_rn(tile[tx][ty + j]);
}

// c[f] = sum_k b1[k] * W2[k][f]   (128 outputs, 1 block x 128 threads)
__global__ void k_bias_c(const float* __restrict__ b1, const float* __restrict__ W2,
                         float* __restrict__ c) {
    int f = threadIdx.x;
    float s = 0.0f;
    for (int k = 0; k < 512; k++) s += b1[k] * W2[(size_t)k * 128 + f];
    c[f] = s;
}

__global__ void k_hist(const void* __restrict__ ei, long long E, int* __restrict__ cnt) {
    long long i = (long long)blockIdx.x * blockDim.x + threadIdx.x;
    if (i >= E) return;
    int d = (int)edge_at(ei, E + i, g_is64);
    atomicAdd(&cnt[d], 1);
}

__global__ void k_scan_blk(const int* __restrict__ cnt, int* __restrict__ rowp,
                           int* __restrict__ bsum, int n) {
    __shared__ int warpsum[32];
    const int t = threadIdx.x, lane = t & 31, w = t >> 5;
    int i = blockIdx.x * 1024 + t;
    int v = (i < n) ? cnt[i] : 0;
    int x = v;
#pragma unroll
    for (int off = 1; off < 32; off <<= 1) {
        int y = __shfl_up_sync(0xFFFFFFFFu, x, off);
        if (lane >= off) x += y;
    }
    if (lane == 31) warpsum[w] = x;
    __syncthreads();
    if (w == 0) {
        int s = warpsum[lane];
#pragma unroll
        for (int off = 1; off < 32; off <<= 1) {
            int y = __shfl_up_sync(0xFFFFFFFFu, s, off);
            if (lane >= off) s += y;
        }
        warpsum[lane] = s;
    }
    __syncthreads();
    int wpre = (w > 0) ? warpsum[w - 1] : 0;
    if (i < n) rowp[i] = x - v + wpre;
    if (t == 1023) bsum[blockIdx.x] = wpre + x;
}

__global__ void k_scan_top(int* __restrict__ bsum, int nb) {
    __shared__ int warpsum[32];
    const int t = threadIdx.x, lane = t & 31, w = t >> 5;
    int v = (t < nb) ? bsum[t] : 0;
    int x = v;
#pragma unroll
    for (int off = 1; off < 32; off <<= 1) {
        int y = __shfl_up_sync(0xFFFFFFFFu, x, off);
        if (lane >= off) x += y;
    }
    if (lane == 31) warpsum[w] = x;
    __syncthreads();
    if (w == 0) {
        int s = warpsum[lane];
#pragma unroll
        for (int off = 1; off < 32; off <<= 1) {
            int y = __shfl_up_sync(0xFFFFFFFFu, s, off);
            if (lane >= off) s += y;
        }
        warpsum[lane] = s;
    }
    __syncthreads();
    int wpre = (w > 0) ? warpsum[w - 1] : 0;
    if (t < nb) bsum[t] = x - v + wpre;
    if (t == 1023) bsum[nb] = warpsum[31];
}

__global__ void k_scan_add(int* __restrict__ rowp, const int* __restrict__ bsum, int n, int nb) {
    int i = blockIdx.x * blockDim.x + threadIdx.x;
    if (i < n) rowp[i] += bsum[i >> 10];
    if (i == n) rowp[n] = bsum[nb];
}

__global__ void k_dinv_cursor(const int* __restrict__ cnt, const int* __restrict__ rowp,
                              float* __restrict__ dinv, int* __restrict__ cur, int n) {
    int i = blockIdx.x * blockDim.x + threadIdx.x;
    if (i >= n) return;
    dinv[i] = rsqrtf((float)cnt[i] + 1.0f);
    cur[i]  = rowp[i];
}

__global__ void k_scatter(const void* __restrict__ ei, long long E,
                          int* __restrict__ cur, int* __restrict__ colA) {
    long long i = (long long)blockIdx.x * blockDim.x + threadIdx.x;
    if (i >= E) return;
    int is64 = g_is64;
    int s = (int)edge_at(ei, i, is64);
    int d = (int)edge_at(ei, E + i, is64);
    int pos = atomicAdd(&cur[d], 1);
    colA[pos] = s;
}

// ---------------------------------------------------------------------------
// GEMM1 (fused, R12-proven): H16[M,512] = A16[M,512] @ Wt[512,512]^T
// Block 128x256 (grid.x=2), 512 threads, warp tile 32x64, BK=32, 3-stage.
// ---------------------------------------------------------------------------
#define G1_SMEM (3 * (8192 + 16384))

__global__ __launch_bounds__(512, 1)
void k_gemm_big(const __half* __restrict__ A, const __half* __restrict__ Bt,
                __half* __restrict__ H)
{
    extern __shared__ __align__(16) char smem[];
    const uint32_t sbA = smem_u32(smem);
    const uint32_t sbB = sbA + 3 * 8192;

    const int t   = threadIdx.x;
    const int L   = t & 31;
    const int wid = t >> 5;
    const int wm  = wid >> 2;
    const int wn  = wid & 3;
    const int g   = L >> 2;
    const int c   = L & 3;
    const int m0  = blockIdx.y * 128;
    const int n0  = blockIdx.x * 256;

    const uint32_t aLane = ((uint32_t)((L >> 4) & 1)) * 128u
                         + (uint32_t)(wm * 32) + (uint32_t)(L & 7) + ((uint32_t)((L >> 3) & 1)) * 8u;
    const uint32_t bLane = ((uint32_t)((L >> 3) & 1)) * 256u
                         + (uint32_t)(wn * 64) + (uint32_t)(L & 7) + ((uint32_t)((L >> 4) & 1)) * 8u;

    const int a_row = t & 127, a_k8 = t >> 7;
    const int b_r0  = t & 255, b_k0 = t >> 8;
    const int b_r1  = b_r0,    b_k1 = b_k0 + 2;

    float acc[2][8][4];
#pragma unroll
    for (int i = 0; i < 2; i++)
#pragma unroll
        for (int j = 0; j < 8; j++)
#pragma unroll
            for (int q = 0; q < 4; q++) acc[i][j][q] = 0.0f;

    auto issue = [&](int kt) {
        const int stg = kt % 3;
        const int k0 = kt * 32;
        cp_async16(sbA + stg * 8192u + (uint32_t)t * 16u,
                   A + (size_t)(m0 + a_row) * 512 + k0 + a_k8 * 8);
        uint32_t bbase = sbB + stg * 16384u;
        cp_async16(bbase + (uint32_t)t * 16u,
                   Bt + (size_t)(n0 + b_r0) * 512 + k0 + b_k0 * 8);
        cp_async16(bbase + (uint32_t)(t + 512) * 16u,
                   Bt + (size_t)(n0 + b_r1) * 512 + k0 + b_k1 * 8);
        CP_COMMIT();
    };

    issue(0);
    issue(1);

    for (int kt = 0; kt < 16; kt++) {
        if (kt + 1 < 16) { CP_WAIT1(); } else { CP_WAIT0(); }
        __syncthreads();

        const int stg = kt % 3;
        const uint32_t aB = sbA + stg * 8192u;
        const uint32_t bB = sbB + stg * 16384u;
#pragma unroll
        for (int kk = 0; kk < 2; kk++) {
            uint32_t af[2][4];
            uint32_t bf[8][2];
#pragma unroll
            for (int fm = 0; fm < 2; fm++)
                ldsm_x4(af[fm][0], af[fm][1], af[fm][2], af[fm][3],
                        aB + (aLane + (uint32_t)(kk * 256 + fm * 16)) * 16u);
#pragma unroll
            for (int p = 0; p < 4; p++)
                ldsm_x4(bf[2 * p][0], bf[2 * p][1], bf[2 * p + 1][0], bf[2 * p + 1][1],
                        bB + (bLane + (uint32_t)(kk * 512 + p * 16)) * 16u);
#pragma unroll
            for (int fm = 0; fm < 2; fm++)
#pragma unroll
                for (int fn = 0; fn < 8; fn++)
                    MMA16816(acc[fm][fn], af[fm], bf[fn]);
        }

        if (kt + 2 < 16) issue(kt + 2);
    }

#pragma unroll
    for (int fm = 0; fm < 2; fm++) {
        int r0 = m0 + wm * 32 + fm * 16 + g;
        int r1 = r0 + 8;
#pragma unroll
        for (int fn = 0; fn < 8; fn++) {
            int col = n0 + wn * 64 + fn * 8 + c * 2;
            __half2 v0 = __floats2half2_rn(acc[fm][fn][0], acc[fm][fn][1]);
            __half2 v1 = __floats2half2_rn(acc[fm][fn][2], acc[fm][fn][3]);
            *(__half2*)&H[(size_t)r0 * 512 + col] = v0;
            *(__half2*)&H[(size_t)r1 * 512 + col] = v1;
        }
    }
}

// ---------------------------------------------------------------------------
// GEMMP: Ps[M,128] = (h16[M,512] @ Wt2[128,512]^T) * dinv[row]  (fp16 out)
// ---------------------------------------------------------------------------
__global__ __launch_bounds__(256, 2)
void k_gemmP(const __half* __restrict__ A, const __half* __restrict__ Bt,
             const float* __restrict__ dinv, __half* __restrict__ Hs, int M)
{
    __shared__ __align__(16) char smem[32768];
    const uint32_t sbA = smem_u32(smem);
    const uint32_t sbB = sbA + 16384;

    const int t   = threadIdx.x;
    const int L   = t & 31;
    const int wid = t >> 5;
    const int wm  = wid >> 1;
    const int wn  = wid & 1;
    const int g   = L >> 2;
    const int c   = L & 3;
    const int m0  = blockIdx.y * 128;

    const uint32_t aLane = ((uint32_t)((L >> 4) & 1)) * 128u
                         + (uint32_t)(wm * 32) + (uint32_t)(L & 7) + ((uint32_t)((L >> 3) & 1)) * 8u;
    const uint32_t bLane = ((uint32_t)((L >> 3) & 1)) * 128u
                         + (uint32_t)(wn * 64) + (uint32_t)(L & 7) + ((uint32_t)((L >> 4) & 1)) * 8u;

    const int s0 = t, s1 = t + 256;
    const int r0s = s0 & 127, k80 = s0 >> 7;
    const int r1s = s1 & 127, k81 = s1 >> 7;
    const bool m0v = (m0 + r0s) < M, m1v = (m0 + r1s) < M;
    const int ar0 = m0v ? (m0 + r0s) : 0;
    const int ar1 = m1v ? (m0 + r1s) : 0;

    float acc[2][8][4];
#pragma unroll
    for (int i = 0; i < 2; i++)
#pragma unroll
        for (int j = 0; j < 8; j++)
#pragma unroll
            for (int q = 0; q < 4; q++) acc[i][j][q] = 0.0f;

    {
        cp_async16(sbA + s0 * 16u, A + (size_t)ar0 * 512 + k80 * 8);
        cp_async16(sbA + s1 * 16u, A + (size_t)ar1 * 512 + k81 * 8);
        cp_async16(sbB + s0 * 16u, Bt + (size_t)r0s * 512 + k80 * 8);
        cp_async16(sbB + s1 * 16u, Bt + (size_t)r1s * 512 + k81 * 8);
        CP_COMMIT();
        CP_WAIT0();
    }
    __syncthreads();

    for (int kt = 0; kt < 16; kt++) {
        const int buf  = kt & 1;
        const int nbuf = 1 - buf;
        const bool nxt = (kt + 1) < 16;

        if (nxt) {
            const int k0 = (kt + 1) * 32;
            cp_async16(sbA + nbuf * 8192u + s0 * 16u, A + (size_t)ar0 * 512 + k0 + k80 * 8);
            cp_async16(sbA + nbuf * 8192u + s1 * 16u, A + (size_t)ar1 * 512 + k0 + k81 * 8);
            cp_async16(sbB + nbuf * 8192u + s0 * 16u, Bt + (size_t)r0s * 512 + k0 + k80 * 8);
            cp_async16(sbB + nbuf * 8192u + s1 * 16u, Bt + (size_t)r1s * 512 + k0 + k81 * 8);
            CP_COMMIT();
        }

        const uint32_t aB = sbA + buf * 8192u;
        const uint32_t bB = sbB + buf * 8192u;
#pragma unroll
        for (int kk = 0; kk < 2; kk++) {
            uint32_t af[2][4];
            uint32_t bf[8][2];
#pragma unroll
            for (int fm = 0; fm < 2; fm++)
                ldsm_x4(af[fm][0], af[fm][1], af[fm][2], af[fm][3],
                        aB + (aLane + (uint32_t)(kk * 256 + fm * 16)) * 16u);
#pragma unroll
            for (int p = 0; p < 4; p++)
                ldsm_x4(bf[2 * p][0], bf[2 * p][1], bf[2 * p + 1][0], bf[2 * p + 1][1],
                        bB + (bLane + (uint32_t)(kk * 256 + p * 16)) * 16u);
#pragma unroll
            for (int fm = 0; fm < 2; fm++)
#pragma unroll
                for (int fn = 0; fn < 8; fn++)
                    MMA16816(acc[fm][fn], af[fm], bf[fn]);
        }

        if (nxt) CP_WAIT0();
        __syncthreads();
    }

#pragma unroll
    for (int fm = 0; fm < 2; fm++) {
        int r0 = m0 + wm * 32 + fm * 16 + g;
        int r1 = r0 + 8;
        float d0 = (r0 < M) ? dinv[r0] : 0.0f;
        float d1 = (r1 < M) ? dinv[r1] : 0.0f;
#pragma unroll
        for (int fn = 0; fn < 8; fn++) {
            int col = wn * 64 + fn * 8 + c * 2;
            if (r0 < M) {
                __half2 v = __floats2half2_rn(acc[fm][fn][0] * d0, acc[fm][fn][1] * d0);
                *(__half2*)&Hs[(size_t)r0 * 128 + col] = v;
            }
            if (r1 < M) {
                __half2 v = __floats2half2_rn(acc[fm][fn][2] * d1, acc[fm][fn][3] * d1);
                *(__half2*)&Hs[(size_t)r1 * 128 + col] = v;
            }
        }
    }
}

// ---------------------------------------------------------------------------
// pullA: u[i] = dinv^2*(Ps[i] + sum Ps[s]) + dinv*c   (fp16 out, 128-wide)
// warp per dst, j = lane (32 uint2 = 128 feats), 4-way unrolled edges.
// ---------------------------------------------------------------------------
__global__ void k_pullA(const int* __restrict__ rowp, const int* __restrict__ colA,
                        const __half* __restrict__ ps, const float* __restrict__ dinv,
                        const float* __restrict__ cvec, __half* __restrict__ u, int n) {
    int idx = blockIdx.x * blockDim.x + threadIdx.x;
    int dst = idx >> 5;
    int j   = idx & 31;
    if (dst >= n) return;
    const uint2* h2p = (const uint2*)ps;

    uint2 sv = h2p[(size_t)dst * 32 + j];
    float2 f0 = __half22float2(*(__half2*)&sv.x), f1 = __half22float2(*(__half2*)&sv.y);
    float4 acc = make_float4(f0.x, f0.y, f1.x, f1.y);

    int e0 = __ldg(&rowp[dst]);
    int e1 = __ldg(&rowp[dst + 1]);
    int e  = e0;
    for (; e + 4 <= e1; e += 4) {
        int s0 = __ldg(&colA[e]);
        int s1 = __ldg(&colA[e + 1]);
        int s2 = __ldg(&colA[e + 2]);
        int s3 = __ldg(&colA[e + 3]);
        uint2 v0 = h2p[(size_t)s0 * 32 + j];
        uint2 v1 = h2p[(size_t)s1 * 32 + j];
        uint2 v2 = h2p[(size_t)s2 * 32 + j];
        uint2 v3 = h2p[(size_t)s3 * 32 + j];
        float2 a0 = __half22float2(*(__half2*)&v0.x), a1 = __half22float2(*(__half2*)&v0.y);
        float2 b0 = __half22float2(*(__half2*)&v1.x), b1 = __half22float2(*(__half2*)&v1.y);
        float2 c0 = __half22float2(*(__half2*)&v2.x), c1 = __half22float2(*(__half2*)&v2.y);
        float2 q0 = __half22float2(*(__half2*)&v3.x), q1 = __half22float2(*(__half2*)&v3.y);
        acc.x += a0.x + b0.x + c0.x + q0.x;
        acc.y += a0.y + b0.y + c0.y + q0.y;
        acc.z += a1.x + b1.x + c1.x + q1.x;
        acc.w += a1.y + b1.y + c1.y + q1.y;
    }
    for (; e < e1; e++) {
        int s = __ldg(&colA[e]);
        uint2 hv = h2p[(size_t)s * 32 + j];
        float2 g0 = __half22float2(*(__half2*)&hv.x), g1 = __half22float2(*(__half2*)&hv.y);
        acc.x += g0.x; acc.y += g0.y; acc.z += g1.x; acc.w += g1.y;
    }

    float d  = dinv[dst];
    float d2 = d * d;
    float4 cc = ((const float4*)cvec)[j];
    __half2 o0 = __floats2half2_rn(acc.x * d2 + cc.x * d, acc.y * d2 + cc.y * d);
    __half2 o1 = __floats2half2_rn(acc.z * d2 + cc.z * d, acc.w * d2 + cc.w * d);
    uint2 ov = make_uint2(*(uint32_t*)&o0, *(uint32_t*)&o1);
    __stcs((uint2*)&((uint2*)u)[(size_t)dst * 32 + j], ov);
}

// ---------------------------------------------------------------------------
// pullB: out[i] = dinv*(u[i] + sum u[s]) + b2   (fp32 out, 128-wide)
// ---------------------------------------------------------------------------
__global__ void k_pullB(const int* __restrict__ rowp, const int* __restrict__ colA,
                        const __half* __restrict__ u, const float* __restrict__ dinv,
                        const float* __restrict__ bias, float* __restrict__ out, int n) {
    int idx = blockIdx.x * blockDim.x + threadIdx.x;
    int dst = idx >> 5;
    int j   = idx & 31;
    if (dst >= n) return;
    const uint2* h2p = (const uint2*)u;

    uint2 sv = h2p[(size_t)dst * 32 + j];
    float2 f0 = __half22float2(*(__half2*)&sv.x), f1 = __half22float2(*(__half2*)&sv.y);
    float4 acc = make_float4(f0.x, f0.y, f1.x, f1.y);

    int e0 = __ldg(&rowp[dst]);
    int e1 = __ldg(&rowp[dst + 1]);
    int e  = e0;
    for (; e + 4 <= e1; e += 4) {
        int s0 = __ldg(&colA[e]);
        int s1 = __ldg(&colA[e + 1]);
        int s2 = __ldg(&colA[e + 2]);
        int s3 = __ldg(&colA[e + 3]);
        uint2 v0 = h2p[(size_t)s0 * 32 + j];
        uint2 v1 = h2p[(size_t)s1 * 32 + j];
        uint2 v2 = h2p[(size_t)s2 * 32 + j];
        uint2 v3 = h2p[(size_t)s3 * 32 + j];
        float2 a0 = __half22float2(*(__half2*)&v0.x), a1 = __half22float2(*(__half2*)&v0.y);
        float2 b0 = __half22float2(*(__half2*)&v1.x), b1 = __half22float2(*(__half2*)&v1.y);
        float2 c0 = __half22float2(*(__half2*)&v2.x), c1 = __half22float2(*(__half2*)&v2.y);
        float2 q0 = __half22float2(*(__half2*)&v3.x), q1 = __half22float2(*(__half2*)&v3.y);
        acc.x += a0.x + b0.x + c0.x + q0.x;
        acc.y += a0.y + b0.y + c0.y + q0.y;
        acc.z += a1.x + b1.x + c1.x + q1.x;
        acc.w += a1.y + b1.y + c1.y + q1.y;
    }
    for (; e < e1; e++) {
        int s = __ldg(&colA[e]);
        uint2 hv = h2p[(size_t)s * 32 + j];
        float2 g0 = __half22float2(*(__half2*)&hv.x), g1 = __half22float2(*(__half2*)&hv.y);
        acc.x += g0.x; acc.y += g0.y; acc.z += g1.x; acc.w += g1.y;
    }

    float d = dinv[dst];
    float4 bb = ((const float4*)bias)[j];
    float4 o = make_float4(bb.x + acc.x * d, bb.y + acc.y * d,
                           bb.z + acc.z * d, bb.w + acc.w * d);
    __stcs(&((float4*)out)[(size_t)dst * 32 + j], o);
}

// ---------------------------------------------------------------------------
extern "C" void kernel_launch(void* const* d_in, const int* in_sizes, int n_in,
                              void* d_out, int out_size) {
    const float* x   = (const float*)d_in[0];
    const void*  ei  = d_in[1];
    const float* W1  = (const float*)d_in[3];
    const float* b1  = (const float*)d_in[4];
    const float* W2  = (const float*)d_in[5];
    const float* b2  = (const float*)d_in[6];
    float*       out = (float*)d_out;

    const long long nelem = (long long)in_sizes[1];
    const long long E     = nelem / 2;
    const int dhid        = in_sizes[4];         // 512
    const int dout        = in_sizes[6];         // 128
    const int din         = in_sizes[3] / dhid;  // 512
    const int n           = in_sizes[0] / din;   // 100000

    __half *xh_p, *h16_p, *ps_p, *u_p, *wt1_p, *wt2_p;
    float *dinv_p, *c_p;
    int *cnt_p, *rowp_p, *cur_p, *col_p, *bsum_p;
    cudaGetSymbolAddress((void**)&xh_p,   g_xh);
    cudaGetSymbolAddress((void**)&h16_p,  g_h16);
    cudaGetSymbolAddress((void**)&ps_p,   g_ps);
    cudaGetSymbolAddress((void**)&u_p,    g_u);
    cudaGetSymbolAddress((void**)&wt1_p,  g_wt1);
    cudaGetSymbolAddress((void**)&wt2_p,  g_wt2);
    cudaGetSymbolAddress((void**)&c_p,    g_c);
    cudaGetSymbolAddress((void**)&dinv_p, g_dinv);
    cudaGetSymbolAddress((void**)&cnt_p,  g_cnt);
    cudaGetSymbolAddress((void**)&rowp_p, g_rowp);
    cudaGetSymbolAddress((void**)&cur_p,  g_cur);
    cudaGetSymbolAddress((void**)&col_p,  g_col);
    cudaGetSymbolAddress((void**)&bsum_p, g_bsum);

    static bool attr_set = false;
    if (!attr_set) {
        cudaFuncSetAttribute(k_gemm_big, cudaFuncAttributeMaxDynamicSharedMemorySize, G1_SMEM);
        attr_set = true;
    }

    const int eb   = (int)((E + 255) / 256);
    const int nb   = (n + 255) / 256;
    const int nblk = (n + 1023) / 1024;
    const int pull_blocks = (int)(((long long)n * 32 + 255) / 256);

    cudaStream_t s0 = 0;
    cudaStream_t sB = g_sh.ok ? g_sh.s : (cudaStream_t)0;
    const bool fork = g_sh.ok;

    if (fork) {
        cudaEventRecord(g_sh.e0, s0);
        cudaStreamWaitEvent(sB, g_sh.e0, 0);
    }

    // stream0: xcvt -> W1^T -> GEMM1
    k_xcvt<<<(MAXN * 64 + 255) / 256, 256, 0, s0>>>(x, n, xh_p);          // 1
    {
        dim3 grid(dhid / 32, din / 32), blk(32, 8);
        k_transpose_h<<<grid, blk, 0, s0>>>(W1, wt1_p, din, dhid);        // 2
    }
    k_init<<<nb, 256, 0, sB>>>(ei, nelem, n, cnt_p);                      // 3 (B)
    {
        dim3 grid(2, (n + 127) / 128);
        k_gemm_big<<<grid, 512, G1_SMEM, s0>>>(xh_p, wt1_p, h16_p);       // 4 (profiled)
    }

    // streamB: graph chain + W2^T + c, all hidden under GEMM1
    k_hist<<<eb, 256, 0, sB>>>(ei, E, cnt_p);
    k_scan_blk<<<nblk, 1024, 0, sB>>>(cnt_p, rowp_p, bsum_p, n);
    k_scan_top<<<1, 1024, 0, sB>>>(bsum_p, nblk);
    k_scan_add<<<(n + 256) / 256, 256, 0, sB>>>(rowp_p, bsum_p, n, nblk);
    k_dinv_cursor<<<nb, 256, 0, sB>>>(cnt_p, rowp_p, dinv_p, cur_p, n);
    k_scatter<<<eb, 256, 0, sB>>>(ei, E, cur_p, col_p);
    {
        dim3 grid(dout / 32, dhid / 32), blk(32, 8);
        k_transpose_h<<<grid, blk, 0, sB>>>(W2, wt2_p, dhid, dout);
    }
    k_bias_c<<<1, 128, 0, sB>>>(b1, W2, c_p);
    if (fork) cudaEventRecord(g_sh.eB, sB);

    // join, then GEMMP -> pullA -> pullB on stream0
    if (fork) cudaStreamWaitEvent(s0, g_sh.eB, 0);
    {
        dim3 grid(1, (n + 127) / 128);
        k_gemmP<<<grid, 256, 0, s0>>>(h16_p, wt2_p, dinv_p, ps_p, n);
    }
    k_pullA<<<pull_blocks, 256, 0, s0>>>(rowp_p, col_p, ps_p, dinv_p, c_p, u_p, n);
    k_pullB<<<pull_blocks, 256, 0, s0>>>(rowp_p, col_p, u_p, dinv_p, b2, out, n);

    (void)n_in; (void)out_size;
}

// round 16
// speedup vs baseline: 2.9244x; 2.2997x over previous
#include <cuda_runtime.h>
#include <cuda_fp16.h>
#include <stdint.h>

// ---------------------------------------------------------------------------
// GCN 2-layer, fully fused (network is linear):
//   W12 = W1 @ W2  (512x128, fp32 accum -> fp16)
//   Ps  = (X @ W12) * dinv[row]                      (fp16, one tensor GEMM)
//   u   = dinv^2 (Ps_self + sum Ps[s]) + dinv*c      (pullA, c = b1 W2)
//   out = dinv (u_self + sum u[s]) + b2              (pullB, fp32)
// Streams: s0: w12t -> (wait hist) gemm_f -> (wait CSR) pullA -> pullB
//          sB: init -> hist -> scan -> dinv -> scatter -> bias_c
// ---------------------------------------------------------------------------

#define MAXN 100352
#define MAXE 1048576

__device__ __half g_w12t[(size_t)128 * 512];   // W12^T fp16 [f][k]
__device__ __half g_ps[(size_t)MAXN * 128];
__device__ __half g_u[(size_t)MAXN * 128];
__device__ float  g_c[128];
__device__ float  g_dinv[MAXN];
__device__ int    g_cnt[MAXN];
__device__ int    g_rowp[MAXN + 1];
__device__ int    g_cur[MAXN];
__device__ int    g_col[MAXE];
__device__ int    g_bsum[1025];
__device__ int    g_is64;

// --------- side stream + events, created pre-main (global ctor) ------------
struct StreamHolder {
    cudaStream_t s;
    cudaEvent_t  e0, eH, eB;
    bool ok;
    StreamHolder() {
        ok = (cudaStreamCreateWithFlags(&s, cudaStreamNonBlocking) == cudaSuccess);
        ok = ok && (cudaEventCreateWithFlags(&e0, cudaEventDisableTiming) == cudaSuccess);
        ok = ok && (cudaEventCreateWithFlags(&eH, cudaEventDisableTiming) == cudaSuccess);
        ok = ok && (cudaEventCreateWithFlags(&eB, cudaEventDisableTiming) == cudaSuccess);
        if (!ok) s = 0;
    }
};
static StreamHolder g_sh;

// ------------------------------- helpers -----------------------------------
__device__ __forceinline__ uint32_t smem_u32(const void* p) {
    uint32_t a;
    asm("{ .reg .u64 t; cvta.to.shared.u64 t, %1; cvt.u32.u64 %0, t; }" : "=r"(a) : "l"(p));
    return a;
}
__device__ __forceinline__ void ldsm_x4(uint32_t& r0, uint32_t& r1, uint32_t& r2, uint32_t& r3,
                                        uint32_t addr) {
    asm volatile("ldmatrix.sync.aligned.m8n8.x4.shared.b16 {%0,%1,%2,%3}, [%4];"
                 : "=r"(r0), "=r"(r1), "=r"(r2), "=r"(r3) : "r"(addr));
}
__device__ __forceinline__ void cp_async16(uint32_t dst, const void* src) {
    asm volatile("cp.async.ca.shared.global [%0], [%1], 16;" :: "r"(dst), "l"(src) : "memory");
}
#define CP_COMMIT() asm volatile("cp.async.commit_group;" ::: "memory")
#define CP_WAIT0()  asm volatile("cp.async.wait_group 0;" ::: "memory")

#define MMA16816(acc, af, bf)                                                  \
    asm volatile(                                                              \
        "mma.sync.aligned.m16n8k16.row.col.f32.f16.f16.f32 "                   \
        "{%0,%1,%2,%3}, {%4,%5,%6,%7}, {%8,%9}, {%0,%1,%2,%3};"                \
        : "+f"((acc)[0]), "+f"((acc)[1]), "+f"((acc)[2]), "+f"((acc)[3])       \
        : "r"((af)[0]), "r"((af)[1]), "r"((af)[2]), "r"((af)[3]),              \
          "r"((bf)[0]), "r"((bf)[1]))

__device__ __forceinline__ long long edge_at(const void* ei, long long idx, int is64) {
    if (is64) return ((const long long*)ei)[idx];
    return (long long)((const int*)ei)[idx];
}

// ---------------------------------------------------------------------------
// W12t[f][k] = sum_j W1[k][j] * W2[j][f]   (fp32 accum, fp16 store)
// grid 512 (k), block 128 (f). W1 row broadcast, W2 row coalesced.
// ---------------------------------------------------------------------------
__global__ void k_w12t(const float* __restrict__ W1, const float* __restrict__ W2,
                       __half* __restrict__ W12t) {
    int k = blockIdx.x;
    int f = threadIdx.x;
    float acc = 0.0f;
#pragma unroll 8
    for (int j = 0; j < 512; j++)
        acc += __ldg(&W1[(size_t)k * 512 + j]) * __ldg(&W2[(size_t)j * 128 + f]);
    W12t[(size_t)f * 512 + k] = __float2half_rn(acc);
}

// c[f] = sum_k b1[k] * W2[k][f]
__global__ void k_bias_c(const float* __restrict__ b1, const float* __restrict__ W2,
                         float* __restrict__ c) {
    int f = threadIdx.x;
    float s = 0.0f;
    for (int k = 0; k < 512; k++) s += b1[k] * W2[(size_t)k * 128 + f];
    c[f] = s;
}

__global__ void k_init(const void* ei, long long nelem, int n, int* cnt) {
    int i = blockIdx.x * blockDim.x + threadIdx.x;
    if (i < n) cnt[i] = 0;
    if (blockIdx.x == 0 && threadIdx.x == 0) {
        const long long* p = (const long long*)ei;
        long long m = 64;
        if (m > nelem / 2) m = nelem / 2;
        int is64 = 1;
        for (long long j = 0; j < m; j++) {
            long long v = p[j];
            if (v < 0 || v >= (long long)n) { is64 = 0; break; }
        }
        g_is64 = is64;
    }
}

__global__ void k_hist(const void* __restrict__ ei, long long E, int* __restrict__ cnt) {
    long long i = (long long)blockIdx.x * blockDim.x + threadIdx.x;
    if (i >= E) return;
    int d = (int)edge_at(ei, E + i, g_is64);
    atomicAdd(&cnt[d], 1);
}

__global__ void k_scan_blk(const int* __restrict__ cnt, int* __restrict__ rowp,
                           int* __restrict__ bsum, int n) {
    __shared__ int warpsum[32];
    const int t = threadIdx.x, lane = t & 31, w = t >> 5;
    int i = blockIdx.x * 1024 + t;
    int v = (i < n) ? cnt[i] : 0;
    int x = v;
#pragma unroll
    for (int off = 1; off < 32; off <<= 1) {
        int y = __shfl_up_sync(0xFFFFFFFFu, x, off);
        if (lane >= off) x += y;
    }
    if (lane == 31) warpsum[w] = x;
    __syncthreads();
    if (w == 0) {
        int s = warpsum[lane];
#pragma unroll
        for (int off = 1; off < 32; off <<= 1) {
            int y = __shfl_up_sync(0xFFFFFFFFu, s, off);
            if (lane >= off) s += y;
        }
        warpsum[lane] = s;
    }
    __syncthreads();
    int wpre = (w > 0) ? warpsum[w - 1] : 0;
    if (i < n) rowp[i] = x - v + wpre;
    if (t == 1023) bsum[blockIdx.x] = wpre + x;
}

__global__ void k_scan_top(int* __restrict__ bsum, int nb) {
    __shared__ int warpsum[32];
    const int t = threadIdx.x, lane = t & 31, w = t >> 5;
    int v = (t < nb) ? bsum[t] : 0;
    int x = v;
#pragma unroll
    for (int off = 1; off < 32; off <<= 1) {
        int y = __shfl_up_sync(0xFFFFFFFFu, x, off);
        if (lane >= off) x += y;
    }
    if (lane == 31) warpsum[w] = x;
    __syncthreads();
    if (w == 0) {
        int s = warpsum[lane];
#pragma unroll
        for (int off = 1; off < 32; off <<= 1) {
            int y = __shfl_up_sync(0xFFFFFFFFu, s, off);
            if (lane >= off) s += y;
        }
        warpsum[lane] = s;
    }
    __syncthreads();
    int wpre = (w > 0) ? warpsum[w - 1] : 0;
    if (t < nb) bsum[t] = x - v + wpre;
    if (t == 1023) bsum[nb] = warpsum[31];
}

__global__ void k_scan_add(int* __restrict__ rowp, const int* __restrict__ bsum, int n, int nb) {
    int i = blockIdx.x * blockDim.x + threadIdx.x;
    if (i < n) rowp[i] += bsum[i >> 10];
    if (i == n) rowp[n] = bsum[nb];
}

__global__ void k_dinv_cursor(const int* __restrict__ cnt, const int* __restrict__ rowp,
                              float* __restrict__ dinv, int* __restrict__ cur, int n) {
    int i = blockIdx.x * blockDim.x + threadIdx.x;
    if (i >= n) return;
    dinv[i] = rsqrtf((float)cnt[i] + 1.0f);
    cur[i]  = rowp[i];
}

__global__ void k_scatter(const void* __restrict__ ei, long long E,
                          int* __restrict__ cur, int* __restrict__ colA) {
    long long i = (long long)blockIdx.x * blockDim.x + threadIdx.x;
    if (i >= E) return;
    int is64 = g_is64;
    int s = (int)edge_at(ei, i, is64);
    int d = (int)edge_at(ei, E + i, is64);
    int pos = atomicAdd(&cur[d], 1);
    colA[pos] = s;
}

// ---------------------------------------------------------------------------
// GEMM_f: Ps[M,128] = (X[M,512] @ W12t[128,512]^T) * rsqrt(cnt[row]+1)
// Block 128x128, 256 threads (8 warps 4x2), warp tile 32x64, BK=32,
// double-buffered: A from fp32 X via LDG+cvt+STS (one stage ahead in regs),
// B via cp.async (one group in flight). fp16 out.
// ---------------------------------------------------------------------------
__global__ __launch_bounds__(256, 2)
void k_gemm_f(const float* __restrict__ X, const __half* __restrict__ Bt,
              const int* __restrict__ cnt, __half* __restrict__ Ps, int M)
{
    __shared__ __align__(16) char smem[32768];  // A 2x8KB @0, B 2x8KB @16384
    const uint32_t sbB = smem_u32(smem) + 16384;
    const uint32_t sbA = smem_u32(smem);

    const int t   = threadIdx.x;
    const int L   = t & 31;
    const int wid = t >> 5;
    const int wm  = wid >> 1;        // 0..3 -> 32 rows
    const int wn  = wid & 1;         // 0..1 -> 64 cols
    const int g   = L >> 2;
    const int c   = L & 3;
    const int m0  = blockIdx.y * 128;

    const uint32_t aLane = ((uint32_t)((L >> 4) & 1)) * 128u
                         + (uint32_t)(wm * 32) + (uint32_t)(L & 7) + ((uint32_t)((L >> 3) & 1)) * 8u;
    const uint32_t bLane = ((uint32_t)((L >> 3) & 1)) * 128u
                         + (uint32_t)(wn * 64) + (uint32_t)(L & 7) + ((uint32_t)((L >> 4) & 1)) * 8u;

    // staging slots: t and t+256; slot s -> row = s&127, k8 = s>>7
    const int r0s = t & 127,        k80 = t >> 7;        // 0..1
    const int r1s = (t + 256) & 127, k81 = (t + 256) >> 7; // 2..3
    const bool v0 = (m0 + r0s) < M, v1 = (m0 + r1s) < M;

    float acc[2][8][4];
#pragma unroll
    for (int i = 0; i < 2; i++)
#pragma unroll
        for (int j = 0; j < 8; j++)
#pragma unroll
            for (int q = 0; q < 4; q++) acc[i][j][q] = 0.0f;

    float4 a00, a01, a10, a11;   // A stage held one ahead

    auto ldA = [&](int kt) {
        const float* p0 = X + (size_t)(m0 + r0s) * 512 + kt * 32 + k80 * 8;
        const float* p1 = X + (size_t)(m0 + r1s) * 512 + kt * 32 + k81 * 8;
        a00 = v0 ? *(const float4*)p0       : make_float4(0, 0, 0, 0);
        a01 = v0 ? *(const float4*)(p0 + 4) : make_float4(0, 0, 0, 0);
        a10 = v1 ? *(const float4*)p1       : make_float4(0, 0, 0, 0);
        a11 = v1 ? *(const float4*)(p1 + 4) : make_float4(0, 0, 0, 0);
    };
    auto stsA = [&](int kt) {
        const int buf = kt & 1;
        __half2 h0 = __floats2half2_rn(a00.x, a00.y), h1 = __floats2half2_rn(a00.z, a00.w);
        __half2 h2 = __floats2half2_rn(a01.x, a01.y), h3 = __floats2half2_rn(a01.z, a01.w);
        *(uint4*)(smem + buf * 8192 + t * 16) =
            make_uint4(*(uint32_t*)&h0, *(uint32_t*)&h1, *(uint32_t*)&h2, *(uint32_t*)&h3);
        __half2 g0 = __floats2half2_rn(a10.x, a10.y), g1 = __floats2half2_rn(a10.z, a10.w);
        __half2 g2 = __floats2half2_rn(a11.x, a11.y), g3 = __floats2half2_rn(a11.z, a11.w);
        *(uint4*)(smem + buf * 8192 + (t + 256) * 16) =
            make_uint4(*(uint32_t*)&g0, *(uint32_t*)&g1, *(uint32_t*)&g2, *(uint32_t*)&g3);
    };
    auto cpB = [&](int kt) {
        const int buf = kt & 1;
        cp_async16(sbB + buf * 8192u + (uint32_t)t * 16u,
                   Bt + (size_t)r0s * 512 + kt * 32 + k80 * 8);
        cp_async16(sbB + buf * 8192u + (uint32_t)(t + 256) * 16u,
                   Bt + (size_t)r1s * 512 + kt * 32 + k81 * 8);
        CP_COMMIT();
    };

    // prologue
    ldA(0); stsA(0);
    ldA(1);
    cpB(0);

    for (int kt = 0; kt < 16; kt++) {
        CP_WAIT0();
        __syncthreads();              // B(kt) + A(kt) published; old bufs retired

        if (kt + 1 < 16) { stsA(kt + 1); cpB(kt + 1); }
        if (kt + 2 < 16) ldA(kt + 2);

        const uint32_t aB = sbA + (uint32_t)(kt & 1) * 8192u;
        const uint32_t bB = sbB + (uint32_t)(kt & 1) * 8192u;
#pragma unroll
        for (int kk = 0; kk < 2; kk++) {
            uint32_t af[2][4];
            uint32_t bf[8][2];
#pragma unroll
            for (int fm = 0; fm < 2; fm++)
                ldsm_x4(af[fm][0], af[fm][1], af[fm][2], af[fm][3],
                        aB + (aLane + (uint32_t)(kk * 256 + fm * 16)) * 16u);
#pragma unroll
            for (int p = 0; p < 4; p++)
                ldsm_x4(bf[2 * p][0], bf[2 * p][1], bf[2 * p + 1][0], bf[2 * p + 1][1],
                        bB + (bLane + (uint32_t)(kk * 256 + p * 16)) * 16u);
#pragma unroll
            for (int fm = 0; fm < 2; fm++)
#pragma unroll
                for (int fn = 0; fn < 8; fn++)
                    MMA16816(acc[fm][fn], af[fm], bf[fn]);
        }
    }

    // epilogue: scale by rsqrt(cnt+1), fp16 store
#pragma unroll
    for (int fm = 0; fm < 2; fm++) {
        int r0 = m0 + wm * 32 + fm * 16 + g;
        int r1 = r0 + 8;
        float d0 = (r0 < M) ? rsqrtf((float)__ldg(&cnt[r0]) + 1.0f) : 0.0f;
        float d1 = (r1 < M) ? rsqrtf((float)__ldg(&cnt[r1]) + 1.0f) : 0.0f;
#pragma unroll
        for (int fn = 0; fn < 8; fn++) {
            int col = wn * 64 + fn * 8 + c * 2;
            if (r0 < M) {
                __half2 v = __floats2half2_rn(acc[fm][fn][0] * d0, acc[fm][fn][1] * d0);
                *(__half2*)&Ps[(size_t)r0 * 128 + col] = v;
            }
            if (r1 < M) {
                __half2 v = __floats2half2_rn(acc[fm][fn][2] * d1, acc[fm][fn][3] * d1);
                *(__half2*)&Ps[(size_t)r1 * 128 + col] = v;
            }
        }
    }
}

// ---------------------------------------------------------------------------
// pullA: u[i] = dinv^2*(Ps[i] + sum Ps[s]) + dinv*c   (fp16 out, 128-wide)
// ---------------------------------------------------------------------------
__global__ void k_pullA(const int* __restrict__ rowp, const int* __restrict__ colA,
                        const __half* __restrict__ ps, const float* __restrict__ dinv,
                        const float* __restrict__ cvec, __half* __restrict__ u, int n) {
    int idx = blockIdx.x * blockDim.x + threadIdx.x;
    int dst = idx >> 5;
    int j   = idx & 31;
    if (dst >= n) return;
    const uint2* h2p = (const uint2*)ps;

    uint2 sv = h2p[(size_t)dst * 32 + j];
    float2 f0 = __half22float2(*(__half2*)&sv.x), f1 = __half22float2(*(__half2*)&sv.y);
    float4 acc = make_float4(f0.x, f0.y, f1.x, f1.y);

    int e0 = __ldg(&rowp[dst]);
    int e1 = __ldg(&rowp[dst + 1]);
    int e  = e0;
    for (; e + 4 <= e1; e += 4) {
        int s0 = __ldg(&colA[e]);
        int s1 = __ldg(&colA[e + 1]);
        int s2 = __ldg(&colA[e + 2]);
        int s3 = __ldg(&colA[e + 3]);
        uint2 v0 = h2p[(size_t)s0 * 32 + j];
        uint2 v1 = h2p[(size_t)s1 * 32 + j];
        uint2 v2 = h2p[(size_t)s2 * 32 + j];
        uint2 v3 = h2p[(size_t)s3 * 32 + j];
        float2 a0 = __half22float2(*(__half2*)&v0.x), a1 = __half22float2(*(__half2*)&v0.y);
        float2 b0 = __half22float2(*(__half2*)&v1.x), b1 = __half22float2(*(__half2*)&v1.y);
        float2 c0 = __half22float2(*(__half2*)&v2.x), c1 = __half22float2(*(__half2*)&v2.y);
        float2 q0 = __half22float2(*(__half2*)&v3.x), q1 = __half22float2(*(__half2*)&v3.y);
        acc.x += a0.x + b0.x + c0.x + q0.x;
        acc.y += a0.y + b0.y + c0.y + q0.y;
        acc.z += a1.x + b1.x + c1.x + q1.x;
        acc.w += a1.y + b1.y + c1.y + q1.y;
    }
    for (; e < e1; e++) {
        int s = __ldg(&colA[e]);
        uint2 hv = h2p[(size_t)s * 32 + j];
        float2 g0 = __half22float2(*(__half2*)&hv.x), g1 = __half22float2(*(__half2*)&hv.y);
        acc.x += g0.x; acc.y += g0.y; acc.z += g1.x; acc.w += g1.y;
    }

    float d  = dinv[dst];
    float d2 = d * d;
    float4 cc = ((const float4*)cvec)[j];
    __half2 o0 = __floats2half2_rn(acc.x * d2 + cc.x * d, acc.y * d2 + cc.y * d);
    __half2 o1 = __floats2half2_rn(acc.z * d2 + cc.z * d, acc.w * d2 + cc.w * d);
    uint2 ov = make_uint2(*(uint32_t*)&o0, *(uint32_t*)&o1);
    __stcs((uint2*)&((uint2*)u)[(size_t)dst * 32 + j], ov);
}

// ---------------------------------------------------------------------------
// pullB: out[i] = dinv*(u[i] + sum u[s]) + b2   (fp32 out, 128-wide)
// ---------------------------------------------------------------------------
__global__ void k_pullB(const int* __restrict__ rowp, const int* __restrict__ colA,
                        const __half* __restrict__ u, const float* __restrict__ dinv,
                        const float* __restrict__ bias, float* __restrict__ out, int n) {
    int idx = blockIdx.x * blockDim.x + threadIdx.x;
    int dst = idx >> 5;
    int j   = idx & 31;
    if (dst >= n) return;
    const uint2* h2p = (const uint2*)u;

    uint2 sv = h2p[(size_t)dst * 32 + j];
    float2 f0 = __half22float2(*(__half2*)&sv.x), f1 = __half22float2(*(__half2*)&sv.y);
    float4 acc = make_float4(f0.x, f0.y, f1.x, f1.y);

    int e0 = __ldg(&rowp[dst]);
    int e1 = __ldg(&rowp[dst + 1]);
    int e  = e0;
    for (; e + 4 <= e1; e += 4) {
        int s0 = __ldg(&colA[e]);
        int s1 = __ldg(&colA[e + 1]);
        int s2 = __ldg(&colA[e + 2]);
        int s3 = __ldg(&colA[e + 3]);
        uint2 v0 = h2p[(size_t)s0 * 32 + j];
        uint2 v1 = h2p[(size_t)s1 * 32 + j];
        uint2 v2 = h2p[(size_t)s2 * 32 + j];
        uint2 v3 = h2p[(size_t)s3 * 32 + j];
        float2 a0 = __half22float2(*(__half2*)&v0.x), a1 = __half22float2(*(__half2*)&v0.y);
        float2 b0 = __half22float2(*(__half2*)&v1.x), b1 = __half22float2(*(__half2*)&v1.y);
        float2 c0 = __half22float2(*(__half2*)&v2.x), c1 = __half22float2(*(__half2*)&v2.y);
        float2 q0 = __half22float2(*(__half2*)&v3.x), q1 = __half22float2(*(__half2*)&v3.y);
        acc.x += a0.x + b0.x + c0.x + q0.x;
        acc.y += a0.y + b0.y + c0.y + q0.y;
        acc.z += a1.x + b1.x + c1.x + q1.x;
        acc.w += a1.y + b1.y + c1.y + q1.y;
    }
    for (; e < e1; e++) {
        int s = __ldg(&colA[e]);
        uint2 hv = h2p[(size_t)s * 32 + j];
        float2 g0 = __half22float2(*(__half2*)&hv.x), g1 = __half22float2(*(__half2*)&hv.y);
        acc.x += g0.x; acc.y += g0.y; acc.z += g1.x; acc.w += g1.y;
    }

    float d = dinv[dst];
    float4 bb = ((const float4*)bias)[j];
    float4 o = make_float4(bb.x + acc.x * d, bb.y + acc.y * d,
                           bb.z + acc.z * d, bb.w + acc.w * d);
    __stcs(&((float4*)out)[(size_t)dst * 32 + j], o);
}

// ---------------------------------------------------------------------------
extern "C" void kernel_launch(void* const* d_in, const int* in_sizes, int n_in,
                              void* d_out, int out_size) {
    const float* x   = (const float*)d_in[0];
    const void*  ei  = d_in[1];
    const float* W1  = (const float*)d_in[3];
    const float* b1  = (const float*)d_in[4];
    const float* W2  = (const float*)d_in[5];
    const float* b2  = (const float*)d_in[6];
    float*       out = (float*)d_out;

    const long long nelem = (long long)in_sizes[1];
    const long long E     = nelem / 2;
    const int dhid        = in_sizes[4];         // 512
    const int din         = in_sizes[3] / dhid;  // 512
    const int n           = in_sizes[0] / din;   // 100000

    __half *w12t_p, *ps_p, *u_p;
    float *dinv_p, *c_p;
    int *cnt_p, *rowp_p, *cur_p, *col_p, *bsum_p;
    cudaGetSymbolAddress((void**)&w12t_p, g_w12t);
    cudaGetSymbolAddress((void**)&ps_p,   g_ps);
    cudaGetSymbolAddress((void**)&u_p,    g_u);
    cudaGetSymbolAddress((void**)&c_p,    g_c);
    cudaGetSymbolAddress((void**)&dinv_p, g_dinv);
    cudaGetSymbolAddress((void**)&cnt_p,  g_cnt);
    cudaGetSymbolAddress((void**)&rowp_p, g_rowp);
    cudaGetSymbolAddress((void**)&cur_p,  g_cur);
    cudaGetSymbolAddress((void**)&col_p,  g_col);
    cudaGetSymbolAddress((void**)&bsum_p, g_bsum);

    const int eb   = (int)((E + 255) / 256);
    const int nb   = (n + 255) / 256;
    const int nblk = (n + 1023) / 1024;
    const int pull_blocks = (int)(((long long)n * 32 + 255) / 256);

    cudaStream_t s0 = 0;
    cudaStream_t sB = g_sh.ok ? g_sh.s : (cudaStream_t)0;
    const bool fork = g_sh.ok;

    if (fork) {
        cudaEventRecord(g_sh.e0, s0);
        cudaStreamWaitEvent(sB, g_sh.e0, 0);
    }

    // 1 (s0): W12^T = (W1 @ W2)^T fp16
    k_w12t<<<512, 128, 0, s0>>>(W1, W2, w12t_p);
    // 2-3 (sB): init + hist
    k_init<<<nb, 256, 0, sB>>>(ei, nelem, n, cnt_p);
    k_hist<<<eb, 256, 0, sB>>>(ei, E, cnt_p);
    if (fork) cudaEventRecord(g_sh.eH, sB);

    // 4 (s0, profiled): the single big GEMM (needs W12t + cnt)
    if (fork) cudaStreamWaitEvent(s0, g_sh.eH, 0);
    {
        dim3 grid(1, (n + 127) / 128);
        k_gemm_f<<<grid, 256, 0, s0>>>(x, w12t_p, cnt_p, ps_p, n);
    }

    // sB: CSR build + c (hidden under GEMM)
    k_scan_blk<<<nblk, 1024, 0, sB>>>(cnt_p, rowp_p, bsum_p, n);
    k_scan_top<<<1, 1024, 0, sB>>>(bsum_p, nblk);
    k_scan_add<<<(n + 256) / 256, 256, 0, sB>>>(rowp_p, bsum_p, n, nblk);
    k_dinv_cursor<<<nb, 256, 0, sB>>>(cnt_p, rowp_p, dinv_p, cur_p, n);
    k_scatter<<<eb, 256, 0, sB>>>(ei, E, cur_p, col_p);
    k_bias_c<<<1, 128, 0, sB>>>(b1, W2, c_p);
    if (fork) cudaEventRecord(g_sh.eB, sB);

    // join, then pullA -> pullB on s0
    if (fork) cudaStreamWaitEvent(s0, g_sh.eB, 0);
    k_pullA<<<pull_blocks, 256, 0, s0>>>(rowp_p, col_p, ps_p, dinv_p, c_p, u_p, n);
    k_pullB<<<pull_blocks, 256, 0, s0>>>(rowp_p, col_p, u_p, dinv_p, b2, out, n);

    (void)n_in; (void)out_size;
}